// round 9
// baseline (speedup 1.0000x reference)
#include <cuda_runtime.h>
#include <cuda_bf16.h>
#include <cstdint>
#include <cstddef>

#define B_    16
#define S_    2048
#define DIN_  256
#define DATT_ 128
#define NTILE ((B_ * S_) / 128)   // 256 row-tiles of 128

// Pre-swizzled bf16 hi/lo tiles (16B chunks). Tile t = flattened rows
// [t*128, (t+1)*128) of [B*S, 128]; within a tile, chunk index = sw_off>>4.
__device__ uint4 g_Qhi[(size_t)NTILE * 2048];
__device__ uint4 g_Qlo[(size_t)NTILE * 2048];
__device__ uint4 g_Khi[(size_t)NTILE * 2048];
__device__ uint4 g_Klo[(size_t)NTILE * 2048];
__device__ uint4 g_Vhi[(size_t)NTILE * 2048];
__device__ uint4 g_Vlo[(size_t)NTILE * 2048];

// ---------------------------------------------------------------------------
// Helpers
// ---------------------------------------------------------------------------
__device__ __forceinline__ uint32_t smem_u32(const void* p) {
    uint32_t a;
    asm("{ .reg .u64 t; cvta.to.shared.u64 t, %1; cvt.u32.u64 %0, t; }"
        : "=r"(a) : "l"(p));
    return a;
}

// Split two fp32 into packed bf16x2 hi/lo words (a -> low half, b -> high half).
__device__ __forceinline__ void split2(float a, float b, uint32_t& hi, uint32_t& lo)
{
    __nv_bfloat16 ah = __float2bfloat16(a), bh = __float2bfloat16(b);
    float ar = a - __bfloat162float(ah), br = b - __bfloat162float(bh);
    __nv_bfloat16 al = __float2bfloat16(ar), bl = __float2bfloat16(br);
    hi = (uint32_t)__bfloat16_as_ushort(ah) | ((uint32_t)__bfloat16_as_ushort(bh) << 16);
    lo = (uint32_t)__bfloat16_as_ushort(al) | ((uint32_t)__bfloat16_as_ushort(bl) << 16);
}

__device__ __forceinline__ void ldsm4(uint32_t& r0, uint32_t& r1, uint32_t& r2,
                                      uint32_t& r3, uint32_t addr)
{
    asm volatile("ldmatrix.sync.aligned.m8n8.x4.shared.b16 {%0,%1,%2,%3}, [%4];"
                 : "=r"(r0), "=r"(r1), "=r"(r2), "=r"(r3) : "r"(addr));
}
__device__ __forceinline__ void ldsm4t(uint32_t& r0, uint32_t& r1, uint32_t& r2,
                                       uint32_t& r3, uint32_t addr)
{
    asm volatile("ldmatrix.sync.aligned.m8n8.x4.trans.shared.b16 {%0,%1,%2,%3}, [%4];"
                 : "=r"(r0), "=r"(r1), "=r"(r2), "=r"(r3) : "r"(addr));
}

__device__ __forceinline__ void mma16816(float* c, const uint32_t* a,
                                         uint32_t b0, uint32_t b1)
{
    asm volatile("mma.sync.aligned.m16n8k16.row.col.f32.bf16.bf16.f32 "
                 "{%0,%1,%2,%3}, {%4,%5,%6,%7}, {%8,%9}, {%0,%1,%2,%3};"
                 : "+f"(c[0]), "+f"(c[1]), "+f"(c[2]), "+f"(c[3])
                 : "r"(a[0]), "r"(a[1]), "r"(a[2]), "r"(a[3]), "r"(b0), "r"(b1));
}

// SMEM tile: 128 rows x 128 bf16 (256 B/row = 16 chunks of 16 B).
// chunk' = chunk ^ (row&7): conflict-free ldmatrix on all patterns.
__device__ __forceinline__ uint32_t sw_off(int row, int chunk)
{
    return (uint32_t)((row << 8) + ((chunk ^ (row & 7)) << 4));
}

#define CPA16(dst, src) \
    asm volatile("cp.async.cg.shared.global [%0], [%1], 16;" \
                 :: "r"(dst), "l"(src) : "memory")
#define CPA_COMMIT() asm volatile("cp.async.commit_group;" ::: "memory")
#define CPA_WAIT(n)  asm volatile("cp.async.wait_group %0;" :: "n"(n) : "memory")

// ---------------------------------------------------------------------------
// Kernel 1: QKV projection, 512 threads = 16 warps (4/SMSP for latency
// hiding). Warp w: rows 16*(w&7), cols 64*(w>>3). K=256 in two 128-halves.
// Emits pre-swizzled bf16 hi/lo tiles; Q pre-scaled by 1/16.
// ---------------------------------------------------------------------------
#define QAH 0
#define QAL 32768
#define QWH 65536
#define QWL 98304
#define QKV_SMEM 131072

__global__ __launch_bounds__(512, 1) void qkv_mma_kernel(
    const float* __restrict__ A,
    const float* __restrict__ Wq,
    const float* __restrict__ Wk,
    const float* __restrict__ Wv)
{
    extern __shared__ char smem[];
    const uint32_t sb = smem_u32(smem);

    const int tid  = threadIdx.x;
    const int wid  = tid >> 5;
    const int ln   = tid & 31;
    const int wq   = wid & 7;      // row block
    const int wh   = wid >> 3;     // col half
    const int tile = blockIdx.x;
    const int row0 = tile * 128;
    const int z    = blockIdx.z;

    const float* W = (z == 0) ? Wq : (z == 1) ? Wk : Wv;
    uint4* OH = (z == 0) ? g_Qhi : (z == 1) ? g_Khi : g_Vhi;
    uint4* OL = (z == 0) ? g_Qlo : (z == 1) ? g_Klo : g_Vlo;

    float oacc[8][4];
    #pragma unroll
    for (int nt = 0; nt < 8; nt++)
        #pragma unroll
        for (int j = 0; j < 4; j++) oacc[nt][j] = 0.0f;

    for (int k0 = 0; k0 < DIN_; k0 += 128) {
        if (k0) __syncthreads();
        // Convert A half: rows m 0..127, cols k0..k0+127.
        #pragma unroll
        for (int it = 0; it < 4; it++) {
            int idx = tid + it * 512;
            int r = idx >> 4, ch = idx & 15;
            const float4* src = (const float4*)&A[(size_t)(row0 + r) * DIN_ + k0 + ch * 8];
            float4 v0 = src[0], v1 = src[1];
            uint32_t h[4], l[4];
            split2(v0.x, v0.y, h[0], l[0]);
            split2(v0.z, v0.w, h[1], l[1]);
            split2(v1.x, v1.y, h[2], l[2]);
            split2(v1.z, v1.w, h[3], l[3]);
            uint32_t a = sw_off(r, ch);
            *(uint4*)(smem + QAH + a) = make_uint4(h[0], h[1], h[2], h[3]);
            *(uint4*)(smem + QAL + a) = make_uint4(l[0], l[1], l[2], l[3]);
        }
        // Convert W half: rows k k0..k0+127, cols n 0..127.
        #pragma unroll
        for (int it = 0; it < 4; it++) {
            int idx = tid + it * 512;
            int r = idx >> 4, ch = idx & 15;
            const float4* src = (const float4*)&W[(size_t)(k0 + r) * DATT_ + ch * 8];
            float4 v0 = src[0], v1 = src[1];
            uint32_t h[4], l[4];
            split2(v0.x, v0.y, h[0], l[0]);
            split2(v0.z, v0.w, h[1], l[1]);
            split2(v1.x, v1.y, h[2], l[2]);
            split2(v1.z, v1.w, h[3], l[3]);
            uint32_t a = sw_off(r, ch);
            *(uint4*)(smem + QWH + a) = make_uint4(h[0], h[1], h[2], h[3]);
            *(uint4*)(smem + QWL + a) = make_uint4(l[0], l[1], l[2], l[3]);
        }
        __syncthreads();

        // O += A W (3-pass split; W via ldmatrix.trans).
        #pragma unroll
        for (int kk = 0; kk < 8; kk++) {
            uint32_t ahi[4], alo[4];
            uint32_t aoff = sw_off(wq * 16 + (ln & 15), kk * 2 + (ln >> 4));
            ldsm4(ahi[0], ahi[1], ahi[2], ahi[3], sb + QAH + aoff);
            ldsm4(alo[0], alo[1], alo[2], alo[3], sb + QAL + aoff);
            #pragma unroll
            for (int nd2 = 0; nd2 < 4; nd2++) {
                int krow = kk * 16 + (ln & 7) + (ln & 8);
                int chnk = wh * 8 + nd2 * 2 + ((ln >> 4) & 1);
                uint32_t woff = sw_off(krow, chnk);
                uint32_t wh_[4], wl_[4];
                ldsm4t(wh_[0], wh_[1], wh_[2], wh_[3], sb + QWH + woff);
                ldsm4t(wl_[0], wl_[1], wl_[2], wl_[3], sb + QWL + woff);
                mma16816(oacc[2 * nd2],     ahi, wh_[0], wh_[1]);
                mma16816(oacc[2 * nd2 + 1], ahi, wh_[2], wh_[3]);
                mma16816(oacc[2 * nd2],     ahi, wl_[0], wl_[1]);
                mma16816(oacc[2 * nd2 + 1], ahi, wl_[2], wl_[3]);
                mma16816(oacc[2 * nd2],     alo, wh_[0], wh_[1]);
                mma16816(oacc[2 * nd2 + 1], alo, wh_[2], wh_[3]);
            }
        }
    }
    __syncthreads();

    // Stage accumulators to fp32 smem (stride 130), then split to global.
    float* stg = (float*)smem;
    const float scale = (z == 0) ? 0.0625f : 1.0f;
    {
        const int r  = wq * 16 + (ln >> 2);
        const int c0 = wh * 64 + 2 * (ln & 3);
        #pragma unroll
        for (int nt = 0; nt < 8; nt++) {
            int c = c0 + nt * 8;
            stg[r * 130 + c]           = oacc[nt][0] * scale;
            stg[r * 130 + c + 1]       = oacc[nt][1] * scale;
            stg[(r + 8) * 130 + c]     = oacc[nt][2] * scale;
            stg[(r + 8) * 130 + c + 1] = oacc[nt][3] * scale;
        }
    }
    __syncthreads();
    #pragma unroll
    for (int it = 0; it < 4; it++) {
        int idx = tid + it * 512;
        int r = idx >> 4, ch = idx & 15;
        const float* p = &stg[r * 130 + ch * 8];
        uint32_t h[4], l[4];
        split2(p[0], p[1], h[0], l[0]);
        split2(p[2], p[3], h[1], l[1]);
        split2(p[4], p[5], h[2], l[2]);
        split2(p[6], p[7], h[3], l[3]);
        size_t cidx = (size_t)tile * 2048 + (sw_off(r, ch) >> 4);
        OH[cidx] = make_uint4(h[0], h[1], h[2], h[3]);
        OL[cidx] = make_uint4(l[0], l[1], l[2], l[3]);
    }
}

// ---------------------------------------------------------------------------
// Kernel 2: mma.sync bf16-split flash attention, 512 threads = 16 warps.
// QK: warp w = (wq = w&7 q-block, wh = w>>3 key-half), sacc[8][4].
// P stored hi/lo into the dead K buffer (swizzled [q][key]).
// PV: warp w = (wq q-block, wh d-half) over all 128 keys, oacc[8][4].
// O is d-partitioned across warp pairs -> no O reduction; lsum reduced via
// a small smem array. V prefetched by cp.async; K reloaded per tile
// (its buffer holds P).
// ---------------------------------------------------------------------------
#define SMQH 0
#define SMQL 32768
#define SMKH 65536
#define SMKL 98304
#define SMVH 131072
#define SMVL 163840
#define SMSUM 196608
#define ATTN_SMEM (196608 + 1024)

__global__ __launch_bounds__(512, 1) void attn_mma_kernel(
    const int* __restrict__ sen_len,
    float* __restrict__ out)
{
    extern __shared__ char smem[];
    const uint32_t sb = smem_u32(smem);

    const int tid = threadIdx.x;
    const int wid = tid >> 5;
    const int ln  = tid & 31;
    const int wq  = wid & 7;
    const int wh  = wid >> 3;
    const int qb  = wq * 16;
    const int b   = blockIdx.x;              // batch fastest -> balanced waves
    const int q0  = blockIdx.y * 128;
    const int L   = sen_len[b];
    const int ntiles = (L + 127) >> 7;
    const size_t tb0 = (size_t)(b * 16) * 2048;

    // ---- Prologue: group0 = [Q, K0], group1 = [V0] ----
    {
        const uint4* QH = g_Qhi + tb0 + (size_t)blockIdx.y * 2048;
        const uint4* QL = g_Qlo + tb0 + (size_t)blockIdx.y * 2048;
        #pragma unroll
        for (int it = 0; it < 4; it++) {
            int c = tid + it * 512;
            CPA16(sb + SMQH + c * 16, QH + c);
            CPA16(sb + SMQL + c * 16, QL + c);
            CPA16(sb + SMKH + c * 16, g_Khi + tb0 + c);
            CPA16(sb + SMKL + c * 16, g_Klo + tb0 + c);
        }
        CPA_COMMIT();
        #pragma unroll
        for (int it = 0; it < 4; it++) {
            int c = tid + it * 512;
            CPA16(sb + SMVH + c * 16, g_Vhi + tb0 + c);
            CPA16(sb + SMVL + c * 16, g_Vlo + tb0 + c);
        }
        CPA_COMMIT();
    }

    float oacc[8][4];
    #pragma unroll
    for (int nt = 0; nt < 8; nt++)
        #pragma unroll
        for (int j = 0; j < 4; j++) oacc[nt][j] = 0.0f;
    float lsum0 = 0.0f, lsum1 = 0.0f;

    for (int t = 0; t < ntiles; t++) {
        CPA_WAIT(1);        // K(t) (and Q on t=0) complete; V(t) may fly
        __syncthreads();    // K visible CTA-wide

        // ---- S = Q K^T over this warp's 64-key half (3-pass split) ----
        float sacc[8][4];
        #pragma unroll
        for (int nt = 0; nt < 8; nt++)
            #pragma unroll
            for (int j = 0; j < 4; j++) sacc[nt][j] = 0.0f;

        #pragma unroll
        for (int kk = 0; kk < 8; kk++) {
            uint32_t ahi[4], alo[4];
            uint32_t aoff = sw_off(qb + (ln & 15), kk * 2 + (ln >> 4));
            ldsm4(ahi[0], ahi[1], ahi[2], ahi[3], sb + SMQH + aoff);
            ldsm4(alo[0], alo[1], alo[2], alo[3], sb + SMQL + aoff);
            #pragma unroll
            for (int nt2 = 0; nt2 < 4; nt2++) {
                int key  = wh * 64 + nt2 * 16 + (ln & 7) + ((ln & 16) >> 1);
                int chnk = kk * 2 + ((ln & 8) >> 3);
                uint32_t boff = sw_off(key, chnk);
                uint32_t bh[4], bl[4];
                ldsm4(bh[0], bh[1], bh[2], bh[3], sb + SMKH + boff);
                ldsm4(bl[0], bl[1], bl[2], bl[3], sb + SMKL + boff);
                mma16816(sacc[2 * nt2],     ahi, bh[0], bh[1]);
                mma16816(sacc[2 * nt2 + 1], ahi, bh[2], bh[3]);
                mma16816(sacc[2 * nt2],     ahi, bl[0], bl[1]);
                mma16816(sacc[2 * nt2 + 1], ahi, bl[2], bl[3]);
                mma16816(sacc[2 * nt2],     alo, bh[0], bh[1]);
                mma16816(sacc[2 * nt2 + 1], alo, bh[2], bh[3]);
            }
        }
        __syncthreads();    // all warps done reading sK before P overwrites it

        // ---- Softmax; store P hi/lo into the K buffer ([q][key] swizzled) ----
        {
            const int g   = ln >> 2;
            const int t4  = ln & 3;
            const int kbs = t * 128 + wh * 64 + 2 * t4;
            #pragma unroll
            for (int nt = 0; nt < 8; nt++) {
                int kcol = kbs + nt * 8;
                float p0 = (kcol     < L) ? __expf(sacc[nt][0]) : 0.f;
                float p1 = (kcol + 1 < L) ? __expf(sacc[nt][1]) : 0.f;
                float p2 = (kcol     < L) ? __expf(sacc[nt][2]) : 0.f;
                float p3 = (kcol + 1 < L) ? __expf(sacc[nt][3]) : 0.f;
                lsum0 += p0 + p1;
                lsum1 += p2 + p3;
                uint32_t h01, l01, h23, l23;
                split2(p0, p1, h01, l01);
                split2(p2, p3, h23, l23);
                int ch = wh * 8 + nt;
                uint32_t a0 = sw_off(qb + g,     ch) + 4 * t4;
                uint32_t a1 = sw_off(qb + g + 8, ch) + 4 * t4;
                *(uint32_t*)(smem + SMKH + a0) = h01;
                *(uint32_t*)(smem + SMKH + a1) = h23;
                *(uint32_t*)(smem + SMKL + a0) = l01;
                *(uint32_t*)(smem + SMKL + a1) = l23;
            }
        }
        CPA_WAIT(0);        // V(t) own-copies complete
        __syncthreads();    // P stores + everyone's V copies visible

        // ---- O += P V over this warp's 64-d half, all 128 keys ----
        #pragma unroll
        for (int kk = 0; kk < 8; kk++) {
            uint32_t phi[4], plo[4];
            uint32_t aoff = sw_off(qb + (ln & 15), kk * 2 + (ln >> 4));
            ldsm4(phi[0], phi[1], phi[2], phi[3], sb + SMKH + aoff);
            ldsm4(plo[0], plo[1], plo[2], plo[3], sb + SMKL + aoff);
            #pragma unroll
            for (int nd2 = 0; nd2 < 4; nd2++) {
                int keyr = kk * 16 + (ln & 7) + (ln & 8);
                int chnk = wh * 8 + nd2 * 2 + ((ln >> 4) & 1);
                uint32_t voff = sw_off(keyr, chnk);
                uint32_t vh[4], vl[4];
                ldsm4t(vh[0], vh[1], vh[2], vh[3], sb + SMVH + voff);
                ldsm4t(vl[0], vl[1], vl[2], vl[3], sb + SMVL + voff);
                mma16816(oacc[2 * nd2],     phi, vh[0], vh[1]);
                mma16816(oacc[2 * nd2 + 1], phi, vh[2], vh[3]);
                mma16816(oacc[2 * nd2],     phi, vl[0], vl[1]);
                mma16816(oacc[2 * nd2 + 1], phi, vl[2], vl[3]);
                mma16816(oacc[2 * nd2],     plo, vh[0], vh[1]);
                mma16816(oacc[2 * nd2 + 1], plo, vh[2], vh[3]);
            }
        }
        __syncthreads();    // sP/sV reads done before next tile's overwrites

        if (t + 1 < ntiles) {
            const size_t tb = tb0 + (size_t)(t + 1) * 2048;
            #pragma unroll
            for (int it = 0; it < 4; it++) {
                int c = tid + it * 512;
                CPA16(sb + SMKH + c * 16, g_Khi + tb + c);
                CPA16(sb + SMKL + c * 16, g_Klo + tb + c);
            }
            CPA_COMMIT();
            #pragma unroll
            for (int it = 0; it < 4; it++) {
                int c = tid + it * 512;
                CPA16(sb + SMVH + c * 16, g_Vhi + tb + c);
                CPA16(sb + SMVL + c * 16, g_Vlo + tb + c);
            }
            CPA_COMMIT();
        }
    }

    // ---- Epilogue: lsum halves reduced via smem, then normalize + store ----
    lsum0 += __shfl_xor_sync(0xffffffffu, lsum0, 1);
    lsum0 += __shfl_xor_sync(0xffffffffu, lsum0, 2);
    lsum1 += __shfl_xor_sync(0xffffffffu, lsum1, 1);
    lsum1 += __shfl_xor_sync(0xffffffffu, lsum1, 2);

    float* ssum = (float*)(smem + SMSUM);
    const int g  = ln >> 2;
    const int t4 = ln & 3;
    if (t4 == 0) {
        ssum[wh * 128 + qb + g]     = lsum0;
        ssum[wh * 128 + qb + g + 8] = lsum1;
    }
    __syncthreads();
    const float inv0 = 1.0f / (ssum[qb + g]     + ssum[128 + qb + g]);
    const float inv1 = 1.0f / (ssum[qb + g + 8] + ssum[128 + qb + g + 8]);

    const int row = q0 + qb + g;
    float* o0 = &out[((size_t)b * S_ + row) * DATT_ + wh * 64];
    float* o1 = &out[((size_t)b * S_ + row + 8) * DATT_ + wh * 64];
    #pragma unroll
    for (int nt = 0; nt < 8; nt++) {
        int c = nt * 8 + 2 * t4;
        *(float2*)(o0 + c) = make_float2(oacc[nt][0] * inv0, oacc[nt][1] * inv0);
        *(float2*)(o1 + c) = make_float2(oacc[nt][2] * inv1, oacc[nt][3] * inv1);
    }
}

// ---------------------------------------------------------------------------
extern "C" void kernel_launch(void* const* d_in, const int* in_sizes, int n_in,
                              void* d_out, int out_size)
{
    (void)in_sizes; (void)n_in; (void)out_size;
    const float* inputs  = (const float*)d_in[0];
    const int*   sen_len = (const int*)  d_in[1];
    const float* Wq      = (const float*)d_in[2];
    const float* Wk      = (const float*)d_in[3];
    const float* Wv      = (const float*)d_in[4];
    float* out = (float*)d_out;

    cudaFuncSetAttribute(qkv_mma_kernel,
                         cudaFuncAttributeMaxDynamicSharedMemorySize, QKV_SMEM);
    qkv_mma_kernel<<<dim3(NTILE, 1, 3), 512, QKV_SMEM>>>(inputs, Wq, Wk, Wv);

    cudaFuncSetAttribute(attn_mma_kernel,
                         cudaFuncAttributeMaxDynamicSharedMemorySize, ATTN_SMEM);
    attn_mma_kernel<<<dim3(B_, S_ / 128), 512, ATTN_SMEM>>>(sen_len, out);
}

// round 10
// speedup vs baseline: 1.0857x; 1.0857x over previous
#include <cuda_runtime.h>
#include <cuda_bf16.h>
#include <cstdint>
#include <cstddef>

#define B_    16
#define S_    2048
#define DIN_  256
#define DATT_ 128
#define NTILE ((B_ * S_) / 128)   // 256 row-tiles of 128

// Pre-swizzled bf16 hi/lo tiles (16B chunks). Tile t = flattened rows
// [t*128, (t+1)*128) of [B*S, 128]; within a tile, chunk index = sw_off>>4.
__device__ uint4 g_Qhi[(size_t)NTILE * 2048];
__device__ uint4 g_Qlo[(size_t)NTILE * 2048];
__device__ uint4 g_Khi[(size_t)NTILE * 2048];
__device__ uint4 g_Klo[(size_t)NTILE * 2048];
__device__ uint4 g_Vhi[(size_t)NTILE * 2048];
__device__ uint4 g_Vlo[(size_t)NTILE * 2048];

// ---------------------------------------------------------------------------
// Helpers
// ---------------------------------------------------------------------------
__device__ __forceinline__ uint32_t smem_u32(const void* p) {
    uint32_t a;
    asm("{ .reg .u64 t; cvta.to.shared.u64 t, %1; cvt.u32.u64 %0, t; }"
        : "=r"(a) : "l"(p));
    return a;
}

// Split two fp32 into packed bf16x2 hi/lo words (a -> low half, b -> high half).
__device__ __forceinline__ void split2(float a, float b, uint32_t& hi, uint32_t& lo)
{
    __nv_bfloat16 ah = __float2bfloat16(a), bh = __float2bfloat16(b);
    float ar = a - __bfloat162float(ah), br = b - __bfloat162float(bh);
    __nv_bfloat16 al = __float2bfloat16(ar), bl = __float2bfloat16(br);
    hi = (uint32_t)__bfloat16_as_ushort(ah) | ((uint32_t)__bfloat16_as_ushort(bh) << 16);
    lo = (uint32_t)__bfloat16_as_ushort(al) | ((uint32_t)__bfloat16_as_ushort(bl) << 16);
}

__device__ __forceinline__ void ldsm4(uint32_t* r, uint32_t addr)
{
    asm volatile("ldmatrix.sync.aligned.m8n8.x4.shared.b16 {%0,%1,%2,%3}, [%4];"
                 : "=r"(r[0]), "=r"(r[1]), "=r"(r[2]), "=r"(r[3]) : "r"(addr));
}
__device__ __forceinline__ void ldsm4t(uint32_t* r, uint32_t addr)
{
    asm volatile("ldmatrix.sync.aligned.m8n8.x4.trans.shared.b16 {%0,%1,%2,%3}, [%4];"
                 : "=r"(r[0]), "=r"(r[1]), "=r"(r[2]), "=r"(r[3]) : "r"(addr));
}

__device__ __forceinline__ void mma16816(float* c, const uint32_t* a,
                                         uint32_t b0, uint32_t b1)
{
    asm volatile("mma.sync.aligned.m16n8k16.row.col.f32.bf16.bf16.f32 "
                 "{%0,%1,%2,%3}, {%4,%5,%6,%7}, {%8,%9}, {%0,%1,%2,%3};"
                 : "+f"(c[0]), "+f"(c[1]), "+f"(c[2]), "+f"(c[3])
                 : "r"(a[0]), "r"(a[1]), "r"(a[2]), "r"(a[3]), "r"(b0), "r"(b1));
}

// SMEM tile: 128 rows x 128 bf16 (256 B/row = 16 chunks of 16 B).
// chunk' = chunk ^ (row&7): conflict-free ldmatrix on all patterns.
__device__ __forceinline__ uint32_t sw_off(int row, int chunk)
{
    return (uint32_t)((row << 8) + ((chunk ^ (row & 7)) << 4));
}

#define CPA16(dst, src) \
    asm volatile("cp.async.cg.shared.global [%0], [%1], 16;" \
                 :: "r"(dst), "l"(src) : "memory")
#define CPA_COMMIT() asm volatile("cp.async.commit_group;" ::: "memory")
#define CPA_WAIT(n)  asm volatile("cp.async.wait_group %0;" :: "n"(n) : "memory")

// ---------------------------------------------------------------------------
// Kernel 1: QKV projection, 512 threads = 16 warps. Warp w: rows 16*(w&7),
// cols 64*(w>>3). K=256 in two 128-halves. Emits pre-swizzled bf16 hi/lo
// tiles; Q pre-scaled by 1/16. (Unchanged from R9 — measured ~101 us.)
// ---------------------------------------------------------------------------
#define QAH 0
#define QAL 32768
#define QWH 65536
#define QWL 98304
#define QKV_SMEM 131072

__global__ __launch_bounds__(512, 1) void qkv_mma_kernel(
    const float* __restrict__ A,
    const float* __restrict__ Wq,
    const float* __restrict__ Wk,
    const float* __restrict__ Wv)
{
    extern __shared__ char smem[];
    const uint32_t sb = smem_u32(smem);

    const int tid  = threadIdx.x;
    const int wid  = tid >> 5;
    const int ln   = tid & 31;
    const int wq   = wid & 7;
    const int wh   = wid >> 3;
    const int tile = blockIdx.x;
    const int row0 = tile * 128;
    const int z    = blockIdx.z;

    const float* W = (z == 0) ? Wq : (z == 1) ? Wk : Wv;
    uint4* OH = (z == 0) ? g_Qhi : (z == 1) ? g_Khi : g_Vhi;
    uint4* OL = (z == 0) ? g_Qlo : (z == 1) ? g_Klo : g_Vlo;

    float oacc[8][4];
    #pragma unroll
    for (int nt = 0; nt < 8; nt++)
        #pragma unroll
        for (int j = 0; j < 4; j++) oacc[nt][j] = 0.0f;

    for (int k0 = 0; k0 < DIN_; k0 += 128) {
        if (k0) __syncthreads();
        #pragma unroll
        for (int it = 0; it < 4; it++) {
            int idx = tid + it * 512;
            int r = idx >> 4, ch = idx & 15;
            const float4* src = (const float4*)&A[(size_t)(row0 + r) * DIN_ + k0 + ch * 8];
            float4 v0 = src[0], v1 = src[1];
            uint32_t h[4], l[4];
            split2(v0.x, v0.y, h[0], l[0]);
            split2(v0.z, v0.w, h[1], l[1]);
            split2(v1.x, v1.y, h[2], l[2]);
            split2(v1.z, v1.w, h[3], l[3]);
            uint32_t a = sw_off(r, ch);
            *(uint4*)(smem + QAH + a) = make_uint4(h[0], h[1], h[2], h[3]);
            *(uint4*)(smem + QAL + a) = make_uint4(l[0], l[1], l[2], l[3]);
        }
        #pragma unroll
        for (int it = 0; it < 4; it++) {
            int idx = tid + it * 512;
            int r = idx >> 4, ch = idx & 15;
            const float4* src = (const float4*)&W[(size_t)(k0 + r) * DATT_ + ch * 8];
            float4 v0 = src[0], v1 = src[1];
            uint32_t h[4], l[4];
            split2(v0.x, v0.y, h[0], l[0]);
            split2(v0.z, v0.w, h[1], l[1]);
            split2(v1.x, v1.y, h[2], l[2]);
            split2(v1.z, v1.w, h[3], l[3]);
            uint32_t a = sw_off(r, ch);
            *(uint4*)(smem + QWH + a) = make_uint4(h[0], h[1], h[2], h[3]);
            *(uint4*)(smem + QWL + a) = make_uint4(l[0], l[1], l[2], l[3]);
        }
        __syncthreads();

        #pragma unroll
        for (int kk = 0; kk < 8; kk++) {
            uint32_t ahi[4], alo[4];
            uint32_t aoff = sw_off(wq * 16 + (ln & 15), kk * 2 + (ln >> 4));
            ldsm4(ahi, sb + QAH + aoff);
            ldsm4(alo, sb + QAL + aoff);
            #pragma unroll
            for (int nd2 = 0; nd2 < 4; nd2++) {
                int krow = kk * 16 + (ln & 7) + (ln & 8);
                int chnk = wh * 8 + nd2 * 2 + ((ln >> 4) & 1);
                uint32_t woff = sw_off(krow, chnk);
                uint32_t wh_[4], wl_[4];
                ldsm4t(wh_, sb + QWH + woff);
                ldsm4t(wl_, sb + QWL + woff);
                mma16816(oacc[2 * nd2],     ahi, wh_[0], wh_[1]);
                mma16816(oacc[2 * nd2 + 1], ahi, wh_[2], wh_[3]);
                mma16816(oacc[2 * nd2],     ahi, wl_[0], wl_[1]);
                mma16816(oacc[2 * nd2 + 1], ahi, wl_[2], wl_[3]);
                mma16816(oacc[2 * nd2],     alo, wh_[0], wh_[1]);
                mma16816(oacc[2 * nd2 + 1], alo, wh_[2], wh_[3]);
            }
        }
    }
    __syncthreads();

    float* stg = (float*)smem;
    const float scale = (z == 0) ? 0.0625f : 1.0f;
    {
        const int r  = wq * 16 + (ln >> 2);
        const int c0 = wh * 64 + 2 * (ln & 3);
        #pragma unroll
        for (int nt = 0; nt < 8; nt++) {
            int c = c0 + nt * 8;
            stg[r * 130 + c]           = oacc[nt][0] * scale;
            stg[r * 130 + c + 1]       = oacc[nt][1] * scale;
            stg[(r + 8) * 130 + c]     = oacc[nt][2] * scale;
            stg[(r + 8) * 130 + c + 1] = oacc[nt][3] * scale;
        }
    }
    __syncthreads();
    #pragma unroll
    for (int it = 0; it < 4; it++) {
        int idx = tid + it * 512;
        int r = idx >> 4, ch = idx & 15;
        const float* p = &stg[r * 130 + ch * 8];
        uint32_t h[4], l[4];
        split2(p[0], p[1], h[0], l[0]);
        split2(p[2], p[3], h[1], l[1]);
        split2(p[4], p[5], h[2], l[2]);
        split2(p[6], p[7], h[3], l[3]);
        size_t cidx = (size_t)tile * 2048 + (sw_off(r, ch) >> 4);
        OH[cidx] = make_uint4(h[0], h[1], h[2], h[3]);
        OL[cidx] = make_uint4(l[0], l[1], l[2], l[3]);
    }
}

// ---------------------------------------------------------------------------
// Kernel 2: mma.sync bf16-split flash attention (R8 structure: 256 threads,
// 8 warps x 16 q-rows, P in registers, pipelined K/V prefetch) with
// micro-scheduled MMA loops: nt2/nd2 processed in PAIRS (4 live
// accumulators -> same-acc reuse distance 4) and B/V fragments
// double-buffered (next pair's ldsm issued before current pair's 12 MMAs).
// ---------------------------------------------------------------------------
#define SMQH 0
#define SMQL 32768
#define SMKH 65536
#define SMKL 98304
#define SMVH 131072
#define SMVL 163840
#define ATTN_SMEM 196608

__global__ __launch_bounds__(256, 1) void attn_mma_kernel(
    const int* __restrict__ sen_len,
    float* __restrict__ out)
{
    extern __shared__ char smem[];
    const uint32_t sb = smem_u32(smem);

    const int tid = threadIdx.x;
    const int wid = tid >> 5;
    const int ln  = tid & 31;
    const int b   = blockIdx.x;              // batch fastest -> balanced waves
    const int q0  = blockIdx.y * 128;
    const int L   = sen_len[b];
    const int ntiles = (L + 127) >> 7;
    const size_t tb0 = (size_t)(b * 16) * 2048;

    // ---- Prologue: group[Q], group[K0], group[V0] ----
    {
        const uint4* QH = g_Qhi + tb0 + (size_t)blockIdx.y * 2048;
        const uint4* QL = g_Qlo + tb0 + (size_t)blockIdx.y * 2048;
        #pragma unroll
        for (int it = 0; it < 8; it++) {
            int c = tid + it * 256;
            CPA16(sb + SMQH + c * 16, QH + c);
            CPA16(sb + SMQL + c * 16, QL + c);
        }
        CPA_COMMIT();
        #pragma unroll
        for (int it = 0; it < 8; it++) {
            int c = tid + it * 256;
            CPA16(sb + SMKH + c * 16, g_Khi + tb0 + c);
            CPA16(sb + SMKL + c * 16, g_Klo + tb0 + c);
        }
        CPA_COMMIT();
        #pragma unroll
        for (int it = 0; it < 8; it++) {
            int c = tid + it * 256;
            CPA16(sb + SMVH + c * 16, g_Vhi + tb0 + c);
            CPA16(sb + SMVL + c * 16, g_Vlo + tb0 + c);
        }
        CPA_COMMIT();
    }

    const int q0w = wid * 16;
    float oacc[16][4];
    #pragma unroll
    for (int nt = 0; nt < 16; nt++)
        #pragma unroll
        for (int j = 0; j < 4; j++) oacc[nt][j] = 0.0f;
    float lsum0 = 0.0f, lsum1 = 0.0f;

    for (int t = 0; t < ntiles; t++) {
        CPA_WAIT(1);
        __syncthreads();

        // ---- S = Q K^T (3-pass split), pair-interleaved + double-buffered ----
        float sacc[16][4];
        #pragma unroll
        for (int nt = 0; nt < 16; nt++)
            #pragma unroll
            for (int j = 0; j < 4; j++) sacc[nt][j] = 0.0f;

        const int keyb = (ln & 7) + ((ln & 16) >> 1);

        #pragma unroll
        for (int kk = 0; kk < 8; kk++) {
            const int chnk = kk * 2 + ((ln & 8) >> 3);
            uint32_t ahi[4], alo[4];
            uint32_t aoff = sw_off(q0w + (ln & 15), kk * 2 + (ln >> 4));
            ldsm4(ahi, sb + SMQH + aoff);
            ldsm4(alo, sb + SMQL + aoff);

            uint32_t bh[2][2][4], bl[2][2][4];   // [buf][key-of-pair][frag]
            ldsm4(bh[0][0], sb + SMKH + sw_off(keyb,      chnk));
            ldsm4(bl[0][0], sb + SMKL + sw_off(keyb,      chnk));
            ldsm4(bh[0][1], sb + SMKH + sw_off(keyb + 16, chnk));
            ldsm4(bl[0][1], sb + SMKL + sw_off(keyb + 16, chnk));

            #pragma unroll
            for (int p = 0; p < 4; p++) {
                const int cur = p & 1, nxt = cur ^ 1;
                if (p < 3) {
                    int ky = keyb + (p + 1) * 32;
                    ldsm4(bh[nxt][0], sb + SMKH + sw_off(ky,      chnk));
                    ldsm4(bl[nxt][0], sb + SMKL + sw_off(ky,      chnk));
                    ldsm4(bh[nxt][1], sb + SMKH + sw_off(ky + 16, chnk));
                    ldsm4(bl[nxt][1], sb + SMKL + sw_off(ky + 16, chnk));
                }
                float* s0 = sacc[4 * p];
                float* s1 = sacc[4 * p + 1];
                float* s2 = sacc[4 * p + 2];
                float* s3 = sacc[4 * p + 3];
                // pass 1: hi * bh   (same-acc distance 4)
                mma16816(s0, ahi, bh[cur][0][0], bh[cur][0][1]);
                mma16816(s1, ahi, bh[cur][0][2], bh[cur][0][3]);
                mma16816(s2, ahi, bh[cur][1][0], bh[cur][1][1]);
                mma16816(s3, ahi, bh[cur][1][2], bh[cur][1][3]);
                // pass 2: hi * bl
                mma16816(s0, ahi, bl[cur][0][0], bl[cur][0][1]);
                mma16816(s1, ahi, bl[cur][0][2], bl[cur][0][3]);
                mma16816(s2, ahi, bl[cur][1][0], bl[cur][1][1]);
                mma16816(s3, ahi, bl[cur][1][2], bl[cur][1][3]);
                // pass 3: lo * bh
                mma16816(s0, alo, bh[cur][0][0], bh[cur][0][1]);
                mma16816(s1, alo, bh[cur][0][2], bh[cur][0][3]);
                mma16816(s2, alo, bh[cur][1][0], bh[cur][1][1]);
                mma16816(s3, alo, bh[cur][1][2], bh[cur][1][3]);
            }
        }

        // ---- sK dead: prefetch K(t+1) (empty group on last tile) ----
        __syncthreads();
        if (t + 1 < ntiles) {
            const size_t tb = tb0 + (size_t)(t + 1) * 2048;
            #pragma unroll
            for (int it = 0; it < 8; it++) {
                int c = tid + it * 256;
                CPA16(sb + SMKH + c * 16, g_Khi + tb + c);
                CPA16(sb + SMKL + c * 16, g_Klo + tb + c);
            }
        }
        CPA_COMMIT();

        // ---- Softmax (registers only; overlaps K(t+1) load) ----
        uint32_t phi[8][4], plo[8][4];
        const int kb = t * 128 + 2 * (ln & 3);
        #pragma unroll
        for (int nt = 0; nt < 16; nt++) {
            int kcol = kb + nt * 8;
            float p0 = (kcol     < L) ? __expf(sacc[nt][0]) : 0.f;
            float p1 = (kcol + 1 < L) ? __expf(sacc[nt][1]) : 0.f;
            float p2 = (kcol     < L) ? __expf(sacc[nt][2]) : 0.f;
            float p3 = (kcol + 1 < L) ? __expf(sacc[nt][3]) : 0.f;
            lsum0 += p0 + p1;
            lsum1 += p2 + p3;
            uint32_t h01, l01, h23, l23;
            split2(p0, p1, h01, l01);
            split2(p2, p3, h23, l23);
            phi[nt >> 1][(nt & 1) * 2]     = h01;
            phi[nt >> 1][(nt & 1) * 2 + 1] = h23;
            plo[nt >> 1][(nt & 1) * 2]     = l01;
            plo[nt >> 1][(nt & 1) * 2 + 1] = l23;
        }

        CPA_WAIT(1);      // V(t) ready (K(t+1) in flight)
        __syncthreads();

        // ---- O += P V (3-pass split), pair-interleaved + double-buffered ----
        const int keyr0 = (ln & 7) + (ln & 8);
        #pragma unroll
        for (int kk = 0; kk < 8; kk++) {
            const int keyr = kk * 16 + keyr0;
            const int ch0  = (ln >> 4) & 1;

            uint32_t vh[2][2][4], vl[2][2][4];   // [buf][d-of-pair][frag]
            ldsm4t(vh[0][0], sb + SMVH + sw_off(keyr, ch0));
            ldsm4t(vl[0][0], sb + SMVL + sw_off(keyr, ch0));
            ldsm4t(vh[0][1], sb + SMVH + sw_off(keyr, ch0 + 2));
            ldsm4t(vl[0][1], sb + SMVL + sw_off(keyr, ch0 + 2));

            #pragma unroll
            for (int p = 0; p < 4; p++) {
                const int cur = p & 1, nxt = cur ^ 1;
                if (p < 3) {
                    int ch = ch0 + (p + 1) * 4;
                    ldsm4t(vh[nxt][0], sb + SMVH + sw_off(keyr, ch));
                    ldsm4t(vl[nxt][0], sb + SMVL + sw_off(keyr, ch));
                    ldsm4t(vh[nxt][1], sb + SMVH + sw_off(keyr, ch + 2));
                    ldsm4t(vl[nxt][1], sb + SMVL + sw_off(keyr, ch + 2));
                }
                float* o0 = oacc[4 * p];
                float* o1 = oacc[4 * p + 1];
                float* o2 = oacc[4 * p + 2];
                float* o3 = oacc[4 * p + 3];
                mma16816(o0, phi[kk], vh[cur][0][0], vh[cur][0][1]);
                mma16816(o1, phi[kk], vh[cur][0][2], vh[cur][0][3]);
                mma16816(o2, phi[kk], vh[cur][1][0], vh[cur][1][1]);
                mma16816(o3, phi[kk], vh[cur][1][2], vh[cur][1][3]);
                mma16816(o0, phi[kk], vl[cur][0][0], vl[cur][0][1]);
                mma16816(o1, phi[kk], vl[cur][0][2], vl[cur][0][3]);
                mma16816(o2, phi[kk], vl[cur][1][0], vl[cur][1][1]);
                mma16816(o3, phi[kk], vl[cur][1][2], vl[cur][1][3]);
                mma16816(o0, plo[kk], vh[cur][0][0], vh[cur][0][1]);
                mma16816(o1, plo[kk], vh[cur][0][2], vh[cur][0][3]);
                mma16816(o2, plo[kk], vh[cur][1][0], vh[cur][1][1]);
                mma16816(o3, plo[kk], vh[cur][1][2], vh[cur][1][3]);
            }
        }

        // ---- sV dead: prefetch V(t+1) (empty group on last tile) ----
        __syncthreads();
        if (t + 1 < ntiles) {
            const size_t tb = tb0 + (size_t)(t + 1) * 2048;
            #pragma unroll
            for (int it = 0; it < 8; it++) {
                int c = tid + it * 256;
                CPA16(sb + SMVH + c * 16, g_Vhi + tb + c);
                CPA16(sb + SMVL + c * 16, g_Vlo + tb + c);
            }
        }
        CPA_COMMIT();
    }
    CPA_WAIT(0);   // drain trailing empty groups

    // ---- Epilogue ----
    #pragma unroll
    for (int off = 1; off < 4; off <<= 1) {
        lsum0 += __shfl_xor_sync(0xffffffffu, lsum0, off);
        lsum1 += __shfl_xor_sync(0xffffffffu, lsum1, off);
    }
    const float inv0 = 1.0f / lsum0;
    const float inv1 = 1.0f / lsum1;

    const int g    = ln >> 2;
    const int tid4 = ln & 3;
    const int row  = q0 + q0w + g;
    // PV pair-mapping: oacc[4p + u] covers d-cols (4p+u)*8 .. +7 (u in 0..3,
    // pair p handles d-chunk pairs {ch0, ch0+2} -> same nt*8 column layout).
    float* o0 = &out[((size_t)b * S_ + row) * DATT_];
    float* o1 = &out[((size_t)b * S_ + row + 8) * DATT_];
    #pragma unroll
    for (int nt = 0; nt < 16; nt++) {
        int c = nt * 8 + 2 * tid4;
        *(float2*)(o0 + c) = make_float2(oacc[nt][0] * inv0, oacc[nt][1] * inv0);
        *(float2*)(o1 + c) = make_float2(oacc[nt][2] * inv1, oacc[nt][3] * inv1);
    }
}

// ---------------------------------------------------------------------------
extern "C" void kernel_launch(void* const* d_in, const int* in_sizes, int n_in,
                              void* d_out, int out_size)
{
    (void)in_sizes; (void)n_in; (void)out_size;
    const float* inputs  = (const float*)d_in[0];
    const int*   sen_len = (const int*)  d_in[1];
    const float* Wq      = (const float*)d_in[2];
    const float* Wk      = (const float*)d_in[3];
    const float* Wv      = (const float*)d_in[4];
    float* out = (float*)d_out;

    cudaFuncSetAttribute(qkv_mma_kernel,
                         cudaFuncAttributeMaxDynamicSharedMemorySize, QKV_SMEM);
    qkv_mma_kernel<<<dim3(NTILE, 1, 3), 512, QKV_SMEM>>>(inputs, Wq, Wk, Wv);

    cudaFuncSetAttribute(attn_mma_kernel,
                         cudaFuncAttributeMaxDynamicSharedMemorySize, ATTN_SMEM);
    attn_mma_kernel<<<dim3(B_, S_ / 128), 256, ATTN_SMEM>>>(sen_len, out);
}

// round 11
// speedup vs baseline: 1.2612x; 1.1617x over previous
#include <cuda_runtime.h>
#include <cuda_bf16.h>
#include <cuda_fp16.h>
#include <cstdint>
#include <cstddef>

#define B_    16
#define S_    2048
#define DIN_  256
#define DATT_ 128
#define NTILE ((B_ * S_) / 128)   // 256 row-tiles of 128

// Pre-swizzled fp16 hi/lo tiles (16B chunks). Tile t = flattened rows
// [t*128, (t+1)*128) of [B*S, 128]; within a tile, chunk index = sw_off>>4.
__device__ uint4 g_Qhi[(size_t)NTILE * 2048];
__device__ uint4 g_Qlo[(size_t)NTILE * 2048];   // written, unused by attention
__device__ uint4 g_Khi[(size_t)NTILE * 2048];
__device__ uint4 g_Klo[(size_t)NTILE * 2048];
__device__ uint4 g_Vhi[(size_t)NTILE * 2048];
__device__ uint4 g_Vlo[(size_t)NTILE * 2048];

// ---------------------------------------------------------------------------
// Helpers
// ---------------------------------------------------------------------------
__device__ __forceinline__ uint32_t smem_u32(const void* p) {
    uint32_t a;
    asm("{ .reg .u64 t; cvta.to.shared.u64 t, %1; cvt.u32.u64 %0, t; }"
        : "=r"(a) : "l"(p));
    return a;
}

// bf16 split (QKV internal compute, 3-pass).
__device__ __forceinline__ void split2(float a, float b, uint32_t& hi, uint32_t& lo)
{
    __nv_bfloat16 ah = __float2bfloat16(a), bh = __float2bfloat16(b);
    float ar = a - __bfloat162float(ah), br = b - __bfloat162float(bh);
    __nv_bfloat16 al = __float2bfloat16(ar), bl = __float2bfloat16(br);
    hi = (uint32_t)__bfloat16_as_ushort(ah) | ((uint32_t)__bfloat16_as_ushort(bh) << 16);
    lo = (uint32_t)__bfloat16_as_ushort(al) | ((uint32_t)__bfloat16_as_ushort(bl) << 16);
}

// fp16 split (attention tiles: 10-bit mantissa -> lo term ~2^-12 relative).
__device__ __forceinline__ void split2h(float a, float b, uint32_t& hi, uint32_t& lo)
{
    __half ah = __float2half_rn(a), bh = __float2half_rn(b);
    float ar = a - __half2float(ah), br = b - __half2float(bh);
    __half al = __float2half_rn(ar), bl = __float2half_rn(br);
    hi = (uint32_t)__half_as_ushort(ah) | ((uint32_t)__half_as_ushort(bh) << 16);
    lo = (uint32_t)__half_as_ushort(al) | ((uint32_t)__half_as_ushort(bl) << 16);
}

// Pack two fp32 -> fp16x2 (a -> low half).
__device__ __forceinline__ uint32_t packh(float a, float b)
{
    return (uint32_t)__half_as_ushort(__float2half_rn(a))
         | ((uint32_t)__half_as_ushort(__float2half_rn(b)) << 16);
}

__device__ __forceinline__ void ldsm4(uint32_t* r, uint32_t addr)
{
    asm volatile("ldmatrix.sync.aligned.m8n8.x4.shared.b16 {%0,%1,%2,%3}, [%4];"
                 : "=r"(r[0]), "=r"(r[1]), "=r"(r[2]), "=r"(r[3]) : "r"(addr));
}
__device__ __forceinline__ void ldsm4t(uint32_t* r, uint32_t addr)
{
    asm volatile("ldmatrix.sync.aligned.m8n8.x4.trans.shared.b16 {%0,%1,%2,%3}, [%4];"
                 : "=r"(r[0]), "=r"(r[1]), "=r"(r[2]), "=r"(r[3]) : "r"(addr));
}

// bf16 mma (QKV internal)
__device__ __forceinline__ void mma16816(float* c, const uint32_t* a,
                                         uint32_t b0, uint32_t b1)
{
    asm volatile("mma.sync.aligned.m16n8k16.row.col.f32.bf16.bf16.f32 "
                 "{%0,%1,%2,%3}, {%4,%5,%6,%7}, {%8,%9}, {%0,%1,%2,%3};"
                 : "+f"(c[0]), "+f"(c[1]), "+f"(c[2]), "+f"(c[3])
                 : "r"(a[0]), "r"(a[1]), "r"(a[2]), "r"(a[3]), "r"(b0), "r"(b1));
}
// fp16 mma (attention)
__device__ __forceinline__ void mma16816h(float* c, const uint32_t* a,
                                          uint32_t b0, uint32_t b1)
{
    asm volatile("mma.sync.aligned.m16n8k16.row.col.f32.f16.f16.f32 "
                 "{%0,%1,%2,%3}, {%4,%5,%6,%7}, {%8,%9}, {%0,%1,%2,%3};"
                 : "+f"(c[0]), "+f"(c[1]), "+f"(c[2]), "+f"(c[3])
                 : "r"(a[0]), "r"(a[1]), "r"(a[2]), "r"(a[3]), "r"(b0), "r"(b1));
}

// SMEM tile: 128 rows x 128 half-words (256 B/row = 16 chunks of 16 B).
// chunk' = chunk ^ (row&7): conflict-free ldmatrix on all patterns.
__device__ __forceinline__ uint32_t sw_off(int row, int chunk)
{
    return (uint32_t)((row << 8) + ((chunk ^ (row & 7)) << 4));
}

#define CPA16(dst, src) \
    asm volatile("cp.async.cg.shared.global [%0], [%1], 16;" \
                 :: "r"(dst), "l"(src) : "memory")
#define CPA_COMMIT() asm volatile("cp.async.commit_group;" ::: "memory")
#define CPA_WAIT(n)  asm volatile("cp.async.wait_group %0;" :: "n"(n) : "memory")

// ---------------------------------------------------------------------------
// Kernel 1: QKV projection, 512 threads = 16 warps, bf16 3-pass internals.
// Emits pre-swizzled fp16 hi/lo tiles; Q pre-scaled by 1/16.
// ---------------------------------------------------------------------------
#define QAH 0
#define QAL 32768
#define QWH 65536
#define QWL 98304
#define QKV_SMEM 131072

__global__ __launch_bounds__(512, 1) void qkv_mma_kernel(
    const float* __restrict__ A,
    const float* __restrict__ Wq,
    const float* __restrict__ Wk,
    const float* __restrict__ Wv)
{
    extern __shared__ char smem[];
    const uint32_t sb = smem_u32(smem);

    const int tid  = threadIdx.x;
    const int wid  = tid >> 5;
    const int ln   = tid & 31;
    const int wq   = wid & 7;
    const int wh   = wid >> 3;
    const int tile = blockIdx.x;
    const int row0 = tile * 128;
    const int z    = blockIdx.z;

    const float* W = (z == 0) ? Wq : (z == 1) ? Wk : Wv;
    uint4* OH = (z == 0) ? g_Qhi : (z == 1) ? g_Khi : g_Vhi;
    uint4* OL = (z == 0) ? g_Qlo : (z == 1) ? g_Klo : g_Vlo;

    float oacc[8][4];
    #pragma unroll
    for (int nt = 0; nt < 8; nt++)
        #pragma unroll
        for (int j = 0; j < 4; j++) oacc[nt][j] = 0.0f;

    for (int k0 = 0; k0 < DIN_; k0 += 128) {
        if (k0) __syncthreads();
        #pragma unroll
        for (int it = 0; it < 4; it++) {
            int idx = tid + it * 512;
            int r = idx >> 4, ch = idx & 15;
            const float4* src = (const float4*)&A[(size_t)(row0 + r) * DIN_ + k0 + ch * 8];
            float4 v0 = src[0], v1 = src[1];
            uint32_t h[4], l[4];
            split2(v0.x, v0.y, h[0], l[0]);
            split2(v0.z, v0.w, h[1], l[1]);
            split2(v1.x, v1.y, h[2], l[2]);
            split2(v1.z, v1.w, h[3], l[3]);
            uint32_t a = sw_off(r, ch);
            *(uint4*)(smem + QAH + a) = make_uint4(h[0], h[1], h[2], h[3]);
            *(uint4*)(smem + QAL + a) = make_uint4(l[0], l[1], l[2], l[3]);
        }
        #pragma unroll
        for (int it = 0; it < 4; it++) {
            int idx = tid + it * 512;
            int r = idx >> 4, ch = idx & 15;
            const float4* src = (const float4*)&W[(size_t)(k0 + r) * DATT_ + ch * 8];
            float4 v0 = src[0], v1 = src[1];
            uint32_t h[4], l[4];
            split2(v0.x, v0.y, h[0], l[0]);
            split2(v0.z, v0.w, h[1], l[1]);
            split2(v1.x, v1.y, h[2], l[2]);
            split2(v1.z, v1.w, h[3], l[3]);
            uint32_t a = sw_off(r, ch);
            *(uint4*)(smem + QWH + a) = make_uint4(h[0], h[1], h[2], h[3]);
            *(uint4*)(smem + QWL + a) = make_uint4(l[0], l[1], l[2], l[3]);
        }
        __syncthreads();

        #pragma unroll
        for (int kk = 0; kk < 8; kk++) {
            uint32_t ahi[4], alo[4];
            uint32_t aoff = sw_off(wq * 16 + (ln & 15), kk * 2 + (ln >> 4));
            ldsm4(ahi, sb + QAH + aoff);
            ldsm4(alo, sb + QAL + aoff);
            #pragma unroll
            for (int nd2 = 0; nd2 < 4; nd2++) {
                int krow = kk * 16 + (ln & 7) + (ln & 8);
                int chnk = wh * 8 + nd2 * 2 + ((ln >> 4) & 1);
                uint32_t woff = sw_off(krow, chnk);
                uint32_t wh_[4], wl_[4];
                ldsm4t(wh_, sb + QWH + woff);
                ldsm4t(wl_, sb + QWL + woff);
                mma16816(oacc[2 * nd2],     ahi, wh_[0], wh_[1]);
                mma16816(oacc[2 * nd2 + 1], ahi, wh_[2], wh_[3]);
                mma16816(oacc[2 * nd2],     ahi, wl_[0], wl_[1]);
                mma16816(oacc[2 * nd2 + 1], ahi, wl_[2], wl_[3]);
                mma16816(oacc[2 * nd2],     alo, wh_[0], wh_[1]);
                mma16816(oacc[2 * nd2 + 1], alo, wh_[2], wh_[3]);
            }
        }
    }
    __syncthreads();

    float* stg = (float*)smem;
    const float scale = (z == 0) ? 0.0625f : 1.0f;
    {
        const int r  = wq * 16 + (ln >> 2);
        const int c0 = wh * 64 + 2 * (ln & 3);
        #pragma unroll
        for (int nt = 0; nt < 8; nt++) {
            int c = c0 + nt * 8;
            stg[r * 130 + c]           = oacc[nt][0] * scale;
            stg[r * 130 + c + 1]       = oacc[nt][1] * scale;
            stg[(r + 8) * 130 + c]     = oacc[nt][2] * scale;
            stg[(r + 8) * 130 + c + 1] = oacc[nt][3] * scale;
        }
    }
    __syncthreads();
    #pragma unroll
    for (int it = 0; it < 4; it++) {
        int idx = tid + it * 512;
        int r = idx >> 4, ch = idx & 15;
        const float* p = &stg[r * 130 + ch * 8];
        uint32_t h[4], l[4];
        split2h(p[0], p[1], h[0], l[0]);
        split2h(p[2], p[3], h[1], l[1]);
        split2h(p[4], p[5], h[2], l[2]);
        split2h(p[6], p[7], h[3], l[3]);
        size_t cidx = (size_t)tile * 2048 + (sw_off(r, ch) >> 4);
        OH[cidx] = make_uint4(h[0], h[1], h[2], h[3]);
        OL[cidx] = make_uint4(l[0], l[1], l[2], l[3]);
    }
}

// ---------------------------------------------------------------------------
// Kernel 2: mma.sync fp16 2-pass flash attention (hi*hi + hi*lo; lo of the
// A-operand dropped -> Q-lo never loaded, P not split). 256 threads,
// 8 warps x 16 q-rows, pipelined K/V prefetch, pair-interleaved MMAs.
// ---------------------------------------------------------------------------
#define SMQH 0
#define SMKH 32768
#define SMKL 65536
#define SMVH 98304
#define SMVL 131072
#define ATTN_SMEM 163840

__global__ __launch_bounds__(256, 1) void attn_mma_kernel(
    const int* __restrict__ sen_len,
    float* __restrict__ out)
{
    extern __shared__ char smem[];
    const uint32_t sb = smem_u32(smem);

    const int tid = threadIdx.x;
    const int wid = tid >> 5;
    const int ln  = tid & 31;
    const int b   = blockIdx.x;              // batch fastest -> balanced waves
    const int q0  = blockIdx.y * 128;
    const int L   = sen_len[b];
    const int ntiles = (L + 127) >> 7;
    const size_t tb0 = (size_t)(b * 16) * 2048;

    // ---- Prologue: group[Q+K0], group[V0] ----
    {
        const uint4* QH = g_Qhi + tb0 + (size_t)blockIdx.y * 2048;
        #pragma unroll
        for (int it = 0; it < 8; it++) {
            int c = tid + it * 256;
            CPA16(sb + SMQH + c * 16, QH + c);
            CPA16(sb + SMKH + c * 16, g_Khi + tb0 + c);
            CPA16(sb + SMKL + c * 16, g_Klo + tb0 + c);
        }
        CPA_COMMIT();
        #pragma unroll
        for (int it = 0; it < 8; it++) {
            int c = tid + it * 256;
            CPA16(sb + SMVH + c * 16, g_Vhi + tb0 + c);
            CPA16(sb + SMVL + c * 16, g_Vlo + tb0 + c);
        }
        CPA_COMMIT();
    }

    const int q0w = wid * 16;
    float oacc[16][4];
    #pragma unroll
    for (int nt = 0; nt < 16; nt++)
        #pragma unroll
        for (int j = 0; j < 4; j++) oacc[nt][j] = 0.0f;
    float lsum0 = 0.0f, lsum1 = 0.0f;

    for (int t = 0; t < ntiles; t++) {
        CPA_WAIT(1);        // Q+K(t) ready; V(t) may fly
        __syncthreads();

        // ---- S = Qhi (Khi + Klo)^T : 2-pass fp16, pair-interleaved ----
        float sacc[16][4];
        #pragma unroll
        for (int nt = 0; nt < 16; nt++)
            #pragma unroll
            for (int j = 0; j < 4; j++) sacc[nt][j] = 0.0f;

        const int keyb = (ln & 7) + ((ln & 16) >> 1);

        #pragma unroll
        for (int kk = 0; kk < 8; kk++) {
            const int chnk = kk * 2 + ((ln & 8) >> 3);
            uint32_t ahi[4];
            ldsm4(ahi, sb + SMQH + sw_off(q0w + (ln & 15), kk * 2 + (ln >> 4)));

            uint32_t bh[2][2][4], bl[2][2][4];   // [buf][key-of-pair][frag]
            ldsm4(bh[0][0], sb + SMKH + sw_off(keyb,      chnk));
            ldsm4(bl[0][0], sb + SMKL + sw_off(keyb,      chnk));
            ldsm4(bh[0][1], sb + SMKH + sw_off(keyb + 16, chnk));
            ldsm4(bl[0][1], sb + SMKL + sw_off(keyb + 16, chnk));

            #pragma unroll
            for (int p = 0; p < 4; p++) {
                const int cur = p & 1, nxt = cur ^ 1;
                if (p < 3) {
                    int ky = keyb + (p + 1) * 32;
                    ldsm4(bh[nxt][0], sb + SMKH + sw_off(ky,      chnk));
                    ldsm4(bl[nxt][0], sb + SMKL + sw_off(ky,      chnk));
                    ldsm4(bh[nxt][1], sb + SMKH + sw_off(ky + 16, chnk));
                    ldsm4(bl[nxt][1], sb + SMKL + sw_off(ky + 16, chnk));
                }
                float* s0 = sacc[4 * p];
                float* s1 = sacc[4 * p + 1];
                float* s2 = sacc[4 * p + 2];
                float* s3 = sacc[4 * p + 3];
                mma16816h(s0, ahi, bh[cur][0][0], bh[cur][0][1]);
                mma16816h(s1, ahi, bh[cur][0][2], bh[cur][0][3]);
                mma16816h(s2, ahi, bh[cur][1][0], bh[cur][1][1]);
                mma16816h(s3, ahi, bh[cur][1][2], bh[cur][1][3]);
                mma16816h(s0, ahi, bl[cur][0][0], bl[cur][0][1]);
                mma16816h(s1, ahi, bl[cur][0][2], bl[cur][0][3]);
                mma16816h(s2, ahi, bl[cur][1][0], bl[cur][1][1]);
                mma16816h(s3, ahi, bl[cur][1][2], bl[cur][1][3]);
            }
        }

        // ---- sK dead: prefetch K(t+1) (empty group on last tile) ----
        __syncthreads();
        if (t + 1 < ntiles) {
            const size_t tb = tb0 + (size_t)(t + 1) * 2048;
            #pragma unroll
            for (int it = 0; it < 8; it++) {
                int c = tid + it * 256;
                CPA16(sb + SMKH + c * 16, g_Khi + tb + c);
                CPA16(sb + SMKL + c * 16, g_Klo + tb + c);
            }
        }
        CPA_COMMIT();

        // ---- Softmax (registers only; P kept as fp16 hi only) ----
        uint32_t phi[8][4];
        const int kb = t * 128 + 2 * (ln & 3);
        #pragma unroll
        for (int nt = 0; nt < 16; nt++) {
            int kcol = kb + nt * 8;
            float p0 = (kcol     < L) ? __expf(sacc[nt][0]) : 0.f;
            float p1 = (kcol + 1 < L) ? __expf(sacc[nt][1]) : 0.f;
            float p2 = (kcol     < L) ? __expf(sacc[nt][2]) : 0.f;
            float p3 = (kcol + 1 < L) ? __expf(sacc[nt][3]) : 0.f;
            lsum0 += p0 + p1;
            lsum1 += p2 + p3;
            phi[nt >> 1][(nt & 1) * 2]     = packh(p0, p1);
            phi[nt >> 1][(nt & 1) * 2 + 1] = packh(p2, p3);
        }

        CPA_WAIT(1);        // V(t) ready (K(t+1) in flight)
        __syncthreads();

        // ---- O += Phi (Vhi + Vlo) : 2-pass fp16, pair-interleaved ----
        const int keyr0 = (ln & 7) + (ln & 8);
        #pragma unroll
        for (int kk = 0; kk < 8; kk++) {
            const int keyr = kk * 16 + keyr0;
            const int ch0  = (ln >> 4) & 1;

            uint32_t vh[2][2][4], vl[2][2][4];   // [buf][d-of-pair][frag]
            ldsm4t(vh[0][0], sb + SMVH + sw_off(keyr, ch0));
            ldsm4t(vl[0][0], sb + SMVL + sw_off(keyr, ch0));
            ldsm4t(vh[0][1], sb + SMVH + sw_off(keyr, ch0 + 2));
            ldsm4t(vl[0][1], sb + SMVL + sw_off(keyr, ch0 + 2));

            #pragma unroll
            for (int p = 0; p < 4; p++) {
                const int cur = p & 1, nxt = cur ^ 1;
                if (p < 3) {
                    int ch = ch0 + (p + 1) * 4;
                    ldsm4t(vh[nxt][0], sb + SMVH + sw_off(keyr, ch));
                    ldsm4t(vl[nxt][0], sb + SMVL + sw_off(keyr, ch));
                    ldsm4t(vh[nxt][1], sb + SMVH + sw_off(keyr, ch + 2));
                    ldsm4t(vl[nxt][1], sb + SMVL + sw_off(keyr, ch + 2));
                }
                float* o0 = oacc[4 * p];
                float* o1 = oacc[4 * p + 1];
                float* o2 = oacc[4 * p + 2];
                float* o3 = oacc[4 * p + 3];
                mma16816h(o0, phi[kk], vh[cur][0][0], vh[cur][0][1]);
                mma16816h(o1, phi[kk], vh[cur][0][2], vh[cur][0][3]);
                mma16816h(o2, phi[kk], vh[cur][1][0], vh[cur][1][1]);
                mma16816h(o3, phi[kk], vh[cur][1][2], vh[cur][1][3]);
                mma16816h(o0, phi[kk], vl[cur][0][0], vl[cur][0][1]);
                mma16816h(o1, phi[kk], vl[cur][0][2], vl[cur][0][3]);
                mma16816h(o2, phi[kk], vl[cur][1][0], vl[cur][1][1]);
                mma16816h(o3, phi[kk], vl[cur][1][2], vl[cur][1][3]);
            }
        }

        // ---- sV dead: prefetch V(t+1) (empty group on last tile) ----
        __syncthreads();
        if (t + 1 < ntiles) {
            const size_t tb = tb0 + (size_t)(t + 1) * 2048;
            #pragma unroll
            for (int it = 0; it < 8; it++) {
                int c = tid + it * 256;
                CPA16(sb + SMVH + c * 16, g_Vhi + tb + c);
                CPA16(sb + SMVL + c * 16, g_Vlo + tb + c);
            }
        }
        CPA_COMMIT();
    }
    CPA_WAIT(0);   // drain trailing empty groups

    // ---- Epilogue ----
    #pragma unroll
    for (int off = 1; off < 4; off <<= 1) {
        lsum0 += __shfl_xor_sync(0xffffffffu, lsum0, off);
        lsum1 += __shfl_xor_sync(0xffffffffu, lsum1, off);
    }
    const float inv0 = 1.0f / lsum0;
    const float inv1 = 1.0f / lsum1;

    const int g    = ln >> 2;
    const int tid4 = ln & 3;
    const int row  = q0 + q0w + g;
    float* o0 = &out[((size_t)b * S_ + row) * DATT_];
    float* o1 = &out[((size_t)b * S_ + row + 8) * DATT_];
    #pragma unroll
    for (int nt = 0; nt < 16; nt++) {
        int c = nt * 8 + 2 * tid4;
        *(float2*)(o0 + c) = make_float2(oacc[nt][0] * inv0, oacc[nt][1] * inv0);
        *(float2*)(o1 + c) = make_float2(oacc[nt][2] * inv1, oacc[nt][3] * inv1);
    }
}

// ---------------------------------------------------------------------------
extern "C" void kernel_launch(void* const* d_in, const int* in_sizes, int n_in,
                              void* d_out, int out_size)
{
    (void)in_sizes; (void)n_in; (void)out_size;
    const float* inputs  = (const float*)d_in[0];
    const int*   sen_len = (const int*)  d_in[1];
    const float* Wq      = (const float*)d_in[2];
    const float* Wk      = (const float*)d_in[3];
    const float* Wv      = (const float*)d_in[4];
    float* out = (float*)d_out;

    cudaFuncSetAttribute(qkv_mma_kernel,
                         cudaFuncAttributeMaxDynamicSharedMemorySize, QKV_SMEM);
    qkv_mma_kernel<<<dim3(NTILE, 1, 3), 512, QKV_SMEM>>>(inputs, Wq, Wk, Wv);

    cudaFuncSetAttribute(attn_mma_kernel,
                         cudaFuncAttributeMaxDynamicSharedMemorySize, ATTN_SMEM);
    attn_mma_kernel<<<dim3(B_, S_ / 128), 256, ATTN_SMEM>>>(sen_len, out);
}

// round 13
// speedup vs baseline: 1.3439x; 1.0656x over previous
#include <cuda_runtime.h>
#include <cuda_bf16.h>
#include <cuda_fp16.h>
#include <cstdint>
#include <cstddef>

#define B_    16
#define S_    2048
#define DIN_  256
#define DATT_ 128
#define NTILE ((B_ * S_) / 128)   // 256 row-tiles of 128

// Pre-swizzled fp16 hi/lo tiles (16B chunks). Tile t = flattened rows
// [t*128, (t+1)*128) of [B*S, 128]; within a tile, chunk index = sw_off>>4.
__device__ uint4 g_Qhi[(size_t)NTILE * 2048];
__device__ uint4 g_Khi[(size_t)NTILE * 2048];
__device__ uint4 g_Klo[(size_t)NTILE * 2048];
__device__ uint4 g_Vhi[(size_t)NTILE * 2048];
__device__ uint4 g_Vlo[(size_t)NTILE * 2048];

// ---------------------------------------------------------------------------
// Helpers
// ---------------------------------------------------------------------------
__device__ __forceinline__ uint32_t smem_u32(const void* p) {
    uint32_t a;
    asm("{ .reg .u64 t; cvta.to.shared.u64 t, %1; cvt.u32.u64 %0, t; }"
        : "=r"(a) : "l"(p));
    return a;
}

// fp16 split (10-bit mantissa -> lo term ~2^-12 relative coverage to 2^-22).
__device__ __forceinline__ void split2h(float a, float b, uint32_t& hi, uint32_t& lo)
{
    __half ah = __float2half_rn(a), bh = __float2half_rn(b);
    float ar = a - __half2float(ah), br = b - __half2float(bh);
    __half al = __float2half_rn(ar), bl = __float2half_rn(br);
    hi = (uint32_t)__half_as_ushort(ah) | ((uint32_t)__half_as_ushort(bh) << 16);
    lo = (uint32_t)__half_as_ushort(al) | ((uint32_t)__half_as_ushort(bl) << 16);
}

// Pack two fp32 -> fp16x2 (a -> low half).
__device__ __forceinline__ uint32_t packh(float a, float b)
{
    return (uint32_t)__half_as_ushort(__float2half_rn(a))
         | ((uint32_t)__half_as_ushort(__float2half_rn(b)) << 16);
}

__device__ __forceinline__ void ldsm4(uint32_t* r, uint32_t addr)
{
    asm volatile("ldmatrix.sync.aligned.m8n8.x4.shared.b16 {%0,%1,%2,%3}, [%4];"
                 : "=r"(r[0]), "=r"(r[1]), "=r"(r[2]), "=r"(r[3]) : "r"(addr));
}
__device__ __forceinline__ void ldsm4t(uint32_t* r, uint32_t addr)
{
    asm volatile("ldmatrix.sync.aligned.m8n8.x4.trans.shared.b16 {%0,%1,%2,%3}, [%4];"
                 : "=r"(r[0]), "=r"(r[1]), "=r"(r[2]), "=r"(r[3]) : "r"(addr));
}

// fp16 mma
__device__ __forceinline__ void mma16816h(float* c, const uint32_t* a,
                                          uint32_t b0, uint32_t b1)
{
    asm volatile("mma.sync.aligned.m16n8k16.row.col.f32.f16.f16.f32 "
                 "{%0,%1,%2,%3}, {%4,%5,%6,%7}, {%8,%9}, {%0,%1,%2,%3};"
                 : "+f"(c[0]), "+f"(c[1]), "+f"(c[2]), "+f"(c[3])
                 : "r"(a[0]), "r"(a[1]), "r"(a[2]), "r"(a[3]), "r"(b0), "r"(b1));
}

// SMEM tile: 128 rows x 128 half-words (256 B/row = 16 chunks of 16 B).
// chunk' = chunk ^ (row&7): conflict-free ldmatrix on all patterns.
__device__ __forceinline__ uint32_t sw_off(int row, int chunk)
{
    return (uint32_t)((row << 8) + ((chunk ^ (row & 7)) << 4));
}

#define CPA16(dst, src) \
    asm volatile("cp.async.cg.shared.global [%0], [%1], 16;" \
                 :: "r"(dst), "l"(src) : "memory")
#define CPA_COMMIT() asm volatile("cp.async.commit_group;" ::: "memory")
#define CPA_WAIT(n)  asm volatile("cp.async.wait_group %0;" :: "n"(n) : "memory")

// ---------------------------------------------------------------------------
// Kernel 1: QKV projection, 512 threads = 16 warps, fp16 2-pass internals
// (A-hi only; W split hi/lo -> MMA count x0.67 vs bf16 3-pass).
// Emits pre-swizzled fp16 hi/lo tiles; Q pre-scaled by 1/16; Q-lo skipped
// (attention never reads it).
// ---------------------------------------------------------------------------
#define QAH 0
#define QWH 32768
#define QWL 65536
#define QKV_SMEM 98304

__global__ __launch_bounds__(512, 1) void qkv_mma_kernel(
    const float* __restrict__ A,
    const float* __restrict__ Wq,
    const float* __restrict__ Wk,
    const float* __restrict__ Wv)
{
    extern __shared__ char smem[];
    const uint32_t sb = smem_u32(smem);

    const int tid  = threadIdx.x;
    const int wid  = tid >> 5;
    const int ln   = tid & 31;
    const int wq   = wid & 7;
    const int wh   = wid >> 3;
    const int tile = blockIdx.x;
    const int row0 = tile * 128;
    const int z    = blockIdx.z;

    const float* W = (z == 0) ? Wq : (z == 1) ? Wk : Wv;
    uint4* OH = (z == 0) ? g_Qhi : (z == 1) ? g_Khi : g_Vhi;
    uint4* OL = (z == 0) ? (uint4*)nullptr : (z == 1) ? g_Klo : g_Vlo;

    float oacc[8][4];
    #pragma unroll
    for (int nt = 0; nt < 8; nt++)
        #pragma unroll
        for (int j = 0; j < 4; j++) oacc[nt][j] = 0.0f;

    for (int k0 = 0; k0 < DIN_; k0 += 128) {
        if (k0) __syncthreads();
        // Convert A half: rows m 0..127, cols k0..k0+127 -> fp16 hi only.
        #pragma unroll
        for (int it = 0; it < 4; it++) {
            int idx = tid + it * 512;
            int r = idx >> 4, ch = idx & 15;
            const float4* src = (const float4*)&A[(size_t)(row0 + r) * DIN_ + k0 + ch * 8];
            float4 v0 = src[0], v1 = src[1];
            uint32_t h0 = packh(v0.x, v0.y);
            uint32_t h1 = packh(v0.z, v0.w);
            uint32_t h2 = packh(v1.x, v1.y);
            uint32_t h3 = packh(v1.z, v1.w);
            *(uint4*)(smem + QAH + sw_off(r, ch)) = make_uint4(h0, h1, h2, h3);
        }
        // Convert W half: rows k k0..k0+127, cols n 0..127 -> fp16 hi/lo.
        #pragma unroll
        for (int it = 0; it < 4; it++) {
            int idx = tid + it * 512;
            int r = idx >> 4, ch = idx & 15;
            const float4* src = (const float4*)&W[(size_t)(k0 + r) * DATT_ + ch * 8];
            float4 v0 = src[0], v1 = src[1];
            uint32_t h[4], l[4];
            split2h(v0.x, v0.y, h[0], l[0]);
            split2h(v0.z, v0.w, h[1], l[1]);
            split2h(v1.x, v1.y, h[2], l[2]);
            split2h(v1.z, v1.w, h[3], l[3]);
            uint32_t a = sw_off(r, ch);
            *(uint4*)(smem + QWH + a) = make_uint4(h[0], h[1], h[2], h[3]);
            *(uint4*)(smem + QWL + a) = make_uint4(l[0], l[1], l[2], l[3]);
        }
        __syncthreads();

        // O += Ahi (Whi + Wlo) : 2-pass fp16.
        #pragma unroll
        for (int kk = 0; kk < 8; kk++) {
            uint32_t ahi[4];
            ldsm4(ahi, sb + QAH + sw_off(wq * 16 + (ln & 15), kk * 2 + (ln >> 4)));
            #pragma unroll
            for (int nd2 = 0; nd2 < 4; nd2++) {
                int krow = kk * 16 + (ln & 7) + (ln & 8);
                int chnk = wh * 8 + nd2 * 2 + ((ln >> 4) & 1);
                uint32_t woff = sw_off(krow, chnk);
                uint32_t wh_[4], wl_[4];
                ldsm4t(wh_, sb + QWH + woff);
                ldsm4t(wl_, sb + QWL + woff);
                mma16816h(oacc[2 * nd2],     ahi, wh_[0], wh_[1]);
                mma16816h(oacc[2 * nd2 + 1], ahi, wh_[2], wh_[3]);
                mma16816h(oacc[2 * nd2],     ahi, wl_[0], wl_[1]);
                mma16816h(oacc[2 * nd2 + 1], ahi, wl_[2], wl_[3]);
            }
        }
    }
    __syncthreads();

    // Stage accumulators to fp32 smem (stride 130), then split to global.
    float* stg = (float*)smem;
    const float scale = (z == 0) ? 0.0625f : 1.0f;
    {
        const int r  = wq * 16 + (ln >> 2);
        const int c0 = wh * 64 + 2 * (ln & 3);
        #pragma unroll
        for (int nt = 0; nt < 8; nt++) {
            int c = c0 + nt * 8;
            stg[r * 130 + c]           = oacc[nt][0] * scale;
            stg[r * 130 + c + 1]       = oacc[nt][1] * scale;
            stg[(r + 8) * 130 + c]     = oacc[nt][2] * scale;
            stg[(r + 8) * 130 + c + 1] = oacc[nt][3] * scale;
        }
    }
    __syncthreads();
    #pragma unroll
    for (int it = 0; it < 4; it++) {
        int idx = tid + it * 512;
        int r = idx >> 4, ch = idx & 15;
        const float* p = &stg[r * 130 + ch * 8];
        uint32_t h[4], l[4];
        split2h(p[0], p[1], h[0], l[0]);
        split2h(p[2], p[3], h[1], l[1]);
        split2h(p[4], p[5], h[2], l[2]);
        split2h(p[6], p[7], h[3], l[3]);
        size_t cidx = (size_t)tile * 2048 + (sw_off(r, ch) >> 4);
        OH[cidx] = make_uint4(h[0], h[1], h[2], h[3]);
        if (OL) OL[cidx] = make_uint4(l[0], l[1], l[2], l[3]);
    }
}

// ---------------------------------------------------------------------------
// Kernel 2: mma.sync fp16 2-pass flash attention (unchanged from R11).
// 256 threads, 8 warps x 16 q-rows, pipelined K/V prefetch.
// ---------------------------------------------------------------------------
#define SMQH 0
#define SMKH 32768
#define SMKL 65536
#define SMVH 98304
#define SMVL 131072
#define ATTN_SMEM 163840

__global__ __launch_bounds__(256, 1) void attn_mma_kernel(
    const int* __restrict__ sen_len,
    float* __restrict__ out)
{
    extern __shared__ char smem[];
    const uint32_t sb = smem_u32(smem);

    const int tid = threadIdx.x;
    const int wid = tid >> 5;
    const int ln  = tid & 31;
    const int b   = blockIdx.x;              // batch fastest -> balanced waves
    const int q0  = blockIdx.y * 128;
    const int L   = sen_len[b];
    const int ntiles = (L + 127) >> 7;
    const size_t tb0 = (size_t)(b * 16) * 2048;

    // ---- Prologue: group[Q+K0], group[V0] ----
    {
        const uint4* QH = g_Qhi + tb0 + (size_t)blockIdx.y * 2048;
        #pragma unroll
        for (int it = 0; it < 8; it++) {
            int c = tid + it * 256;
            CPA16(sb + SMQH + c * 16, QH + c);
            CPA16(sb + SMKH + c * 16, g_Khi + tb0 + c);
            CPA16(sb + SMKL + c * 16, g_Klo + tb0 + c);
        }
        CPA_COMMIT();
        #pragma unroll
        for (int it = 0; it < 8; it++) {
            int c = tid + it * 256;
            CPA16(sb + SMVH + c * 16, g_Vhi + tb0 + c);
            CPA16(sb + SMVL + c * 16, g_Vlo + tb0 + c);
        }
        CPA_COMMIT();
    }

    const int q0w = wid * 16;
    float oacc[16][4];
    #pragma unroll
    for (int nt = 0; nt < 16; nt++)
        #pragma unroll
        for (int j = 0; j < 4; j++) oacc[nt][j] = 0.0f;
    float lsum0 = 0.0f, lsum1 = 0.0f;

    for (int t = 0; t < ntiles; t++) {
        CPA_WAIT(1);        // Q+K(t) ready; V(t) may fly
        __syncthreads();

        // ---- S = Qhi (Khi + Klo)^T : 2-pass fp16, pair-interleaved ----
        float sacc[16][4];
        #pragma unroll
        for (int nt = 0; nt < 16; nt++)
            #pragma unroll
            for (int j = 0; j < 4; j++) sacc[nt][j] = 0.0f;

        const int keyb = (ln & 7) + ((ln & 16) >> 1);

        #pragma unroll
        for (int kk = 0; kk < 8; kk++) {
            const int chnk = kk * 2 + ((ln & 8) >> 3);
            uint32_t ahi[4];
            ldsm4(ahi, sb + SMQH + sw_off(q0w + (ln & 15), kk * 2 + (ln >> 4)));

            uint32_t bh[2][2][4], bl[2][2][4];   // [buf][key-of-pair][frag]
            ldsm4(bh[0][0], sb + SMKH + sw_off(keyb,      chnk));
            ldsm4(bl[0][0], sb + SMKL + sw_off(keyb,      chnk));
            ldsm4(bh[0][1], sb + SMKH + sw_off(keyb + 16, chnk));
            ldsm4(bl[0][1], sb + SMKL + sw_off(keyb + 16, chnk));

            #pragma unroll
            for (int p = 0; p < 4; p++) {
                const int cur = p & 1, nxt = cur ^ 1;
                if (p < 3) {
                    int ky = keyb + (p + 1) * 32;
                    ldsm4(bh[nxt][0], sb + SMKH + sw_off(ky,      chnk));
                    ldsm4(bl[nxt][0], sb + SMKL + sw_off(ky,      chnk));
                    ldsm4(bh[nxt][1], sb + SMKH + sw_off(ky + 16, chnk));
                    ldsm4(bl[nxt][1], sb + SMKL + sw_off(ky + 16, chnk));
                }
                float* s0 = sacc[4 * p];
                float* s1 = sacc[4 * p + 1];
                float* s2 = sacc[4 * p + 2];
                float* s3 = sacc[4 * p + 3];
                mma16816h(s0, ahi, bh[cur][0][0], bh[cur][0][1]);
                mma16816h(s1, ahi, bh[cur][0][2], bh[cur][0][3]);
                mma16816h(s2, ahi, bh[cur][1][0], bh[cur][1][1]);
                mma16816h(s3, ahi, bh[cur][1][2], bh[cur][1][3]);
                mma16816h(s0, ahi, bl[cur][0][0], bl[cur][0][1]);
                mma16816h(s1, ahi, bl[cur][0][2], bl[cur][0][3]);
                mma16816h(s2, ahi, bl[cur][1][0], bl[cur][1][1]);
                mma16816h(s3, ahi, bl[cur][1][2], bl[cur][1][3]);
            }
        }

        // ---- sK dead: prefetch K(t+1) (empty group on last tile) ----
        __syncthreads();
        if (t + 1 < ntiles) {
            const size_t tb = tb0 + (size_t)(t + 1) * 2048;
            #pragma unroll
            for (int it = 0; it < 8; it++) {
                int c = tid + it * 256;
                CPA16(sb + SMKH + c * 16, g_Khi + tb + c);
                CPA16(sb + SMKL + c * 16, g_Klo + tb + c);
            }
        }
        CPA_COMMIT();

        // ---- Softmax (registers only; P kept as fp16 hi only) ----
        uint32_t phi[8][4];
        const int kb = t * 128 + 2 * (ln & 3);
        #pragma unroll
        for (int nt = 0; nt < 16; nt++) {
            int kcol = kb + nt * 8;
            float p0 = (kcol     < L) ? __expf(sacc[nt][0]) : 0.f;
            float p1 = (kcol + 1 < L) ? __expf(sacc[nt][1]) : 0.f;
            float p2 = (kcol     < L) ? __expf(sacc[nt][2]) : 0.f;
            float p3 = (kcol + 1 < L) ? __expf(sacc[nt][3]) : 0.f;
            lsum0 += p0 + p1;
            lsum1 += p2 + p3;
            phi[nt >> 1][(nt & 1) * 2]     = packh(p0, p1);
            phi[nt >> 1][(nt & 1) * 2 + 1] = packh(p2, p3);
        }

        CPA_WAIT(1);        // V(t) ready (K(t+1) in flight)
        __syncthreads();

        // ---- O += Phi (Vhi + Vlo) : 2-pass fp16, pair-interleaved ----
        const int keyr0 = (ln & 7) + (ln & 8);
        #pragma unroll
        for (int kk = 0; kk < 8; kk++) {
            const int keyr = kk * 16 + keyr0;
            const int ch0  = (ln >> 4) & 1;

            uint32_t vh[2][2][4], vl[2][2][4];   // [buf][d-of-pair][frag]
            ldsm4t(vh[0][0], sb + SMVH + sw_off(keyr, ch0));
            ldsm4t(vl[0][0], sb + SMVL + sw_off(keyr, ch0));
            ldsm4t(vh[0][1], sb + SMVH + sw_off(keyr, ch0 + 2));
            ldsm4t(vl[0][1], sb + SMVL + sw_off(keyr, ch0 + 2));

            #pragma unroll
            for (int p = 0; p < 4; p++) {
                const int cur = p & 1, nxt = cur ^ 1;
                if (p < 3) {
                    int ch = ch0 + (p + 1) * 4;
                    ldsm4t(vh[nxt][0], sb + SMVH + sw_off(keyr, ch));
                    ldsm4t(vl[nxt][0], sb + SMVL + sw_off(keyr, ch));
                    ldsm4t(vh[nxt][1], sb + SMVH + sw_off(keyr, ch + 2));
                    ldsm4t(vl[nxt][1], sb + SMVL + sw_off(keyr, ch + 2));
                }
                float* o0 = oacc[4 * p];
                float* o1 = oacc[4 * p + 1];
                float* o2 = oacc[4 * p + 2];
                float* o3 = oacc[4 * p + 3];
                mma16816h(o0, phi[kk], vh[cur][0][0], vh[cur][0][1]);
                mma16816h(o1, phi[kk], vh[cur][0][2], vh[cur][0][3]);
                mma16816h(o2, phi[kk], vh[cur][1][0], vh[cur][1][1]);
                mma16816h(o3, phi[kk], vh[cur][1][2], vh[cur][1][3]);
                mma16816h(o0, phi[kk], vl[cur][0][0], vl[cur][0][1]);
                mma16816h(o1, phi[kk], vl[cur][0][2], vl[cur][0][3]);
                mma16816h(o2, phi[kk], vl[cur][1][0], vl[cur][1][1]);
                mma16816h(o3, phi[kk], vl[cur][1][2], vl[cur][1][3]);
            }
        }

        // ---- sV dead: prefetch V(t+1) (empty group on last tile) ----
        __syncthreads();
        if (t + 1 < ntiles) {
            const size_t tb = tb0 + (size_t)(t + 1) * 2048;
            #pragma unroll
            for (int it = 0; it < 8; it++) {
                int c = tid + it * 256;
                CPA16(sb + SMVH + c * 16, g_Vhi + tb + c);
                CPA16(sb + SMVL + c * 16, g_Vlo + tb + c);
            }
        }
        CPA_COMMIT();
    }
    CPA_WAIT(0);   // drain trailing empty groups

    // ---- Epilogue ----
    #pragma unroll
    for (int off = 1; off < 4; off <<= 1) {
        lsum0 += __shfl_xor_sync(0xffffffffu, lsum0, off);
        lsum1 += __shfl_xor_sync(0xffffffffu, lsum1, off);
    }
    const float inv0 = 1.0f / lsum0;
    const float inv1 = 1.0f / lsum1;

    const int g    = ln >> 2;
    const int tid4 = ln & 3;
    const int row  = q0 + q0w + g;
    float* o0 = &out[((size_t)b * S_ + row) * DATT_];
    float* o1 = &out[((size_t)b * S_ + row + 8) * DATT_];
    #pragma unroll
    for (int nt = 0; nt < 16; nt++) {
        int c = nt * 8 + 2 * tid4;
        *(float2*)(o0 + c) = make_float2(oacc[nt][0] * inv0, oacc[nt][1] * inv0);
        *(float2*)(o1 + c) = make_float2(oacc[nt][2] * inv1, oacc[nt][3] * inv1);
    }
}

// ---------------------------------------------------------------------------
extern "C" void kernel_launch(void* const* d_in, const int* in_sizes, int n_in,
                              void* d_out, int out_size)
{
    (void)in_sizes; (void)n_in; (void)out_size;
    const float* inputs  = (const float*)d_in[0];
    const int*   sen_len = (const int*)  d_in[1];
    const float* Wq      = (const float*)d_in[2];
    const float* Wk      = (const float*)d_in[3];
    const float* Wv      = (const float*)d_in[4];
    float* out = (float*)d_out;

    cudaFuncSetAttribute(qkv_mma_kernel,
                         cudaFuncAttributeMaxDynamicSharedMemorySize, QKV_SMEM);
    qkv_mma_kernel<<<dim3(NTILE, 1, 3), 512, QKV_SMEM>>>(inputs, Wq, Wk, Wv);

    cudaFuncSetAttribute(attn_mma_kernel,
                         cudaFuncAttributeMaxDynamicSharedMemorySize, ATTN_SMEM);
    attn_mma_kernel<<<dim3(B_, S_ / 128), 256, ATTN_SMEM>>>(sen_len, out);
}

// round 14
// speedup vs baseline: 1.8842x; 1.4020x over previous
#include <cuda_runtime.h>
#include <cuda_bf16.h>
#include <cuda_fp16.h>
#include <cstdint>
#include <cstddef>

#define B_    16
#define S_    2048
#define DIN_  256
#define DATT_ 128
#define NTILE ((B_ * S_) / 128)   // 256 row-tiles of 128

// Pre-swizzled fp16 hi/lo tiles (16B chunks). Tile t = flattened rows
// [t*128, (t+1)*128) of [B*S, 128]; within a tile, chunk index = sw_off>>4.
__device__ uint4 g_Qhi[(size_t)NTILE * 2048];
__device__ uint4 g_Khi[(size_t)NTILE * 2048];
__device__ uint4 g_Klo[(size_t)NTILE * 2048];
__device__ uint4 g_Vhi[(size_t)NTILE * 2048];
__device__ uint4 g_Vlo[(size_t)NTILE * 2048];

// LPT batch order (sorted by sen_len descending).
__device__ int g_perm[B_];

// ---------------------------------------------------------------------------
// Helpers
// ---------------------------------------------------------------------------
__device__ __forceinline__ uint32_t smem_u32(const void* p) {
    uint32_t a;
    asm("{ .reg .u64 t; cvta.to.shared.u64 t, %1; cvt.u32.u64 %0, t; }"
        : "=r"(a) : "l"(p));
    return a;
}

// fp16 split (10-bit mantissa -> lo term ~2^-12 relative coverage to 2^-22).
__device__ __forceinline__ void split2h(float a, float b, uint32_t& hi, uint32_t& lo)
{
    __half ah = __float2half_rn(a), bh = __float2half_rn(b);
    float ar = a - __half2float(ah), br = b - __half2float(bh);
    __half al = __float2half_rn(ar), bl = __float2half_rn(br);
    hi = (uint32_t)__half_as_ushort(ah) | ((uint32_t)__half_as_ushort(bh) << 16);
    lo = (uint32_t)__half_as_ushort(al) | ((uint32_t)__half_as_ushort(bl) << 16);
}

// Pack two fp32 -> fp16x2 (a -> low half).
__device__ __forceinline__ uint32_t packh(float a, float b)
{
    return (uint32_t)__half_as_ushort(__float2half_rn(a))
         | ((uint32_t)__half_as_ushort(__float2half_rn(b)) << 16);
}

__device__ __forceinline__ void ldsm4(uint32_t* r, uint32_t addr)
{
    asm volatile("ldmatrix.sync.aligned.m8n8.x4.shared.b16 {%0,%1,%2,%3}, [%4];"
                 : "=r"(r[0]), "=r"(r[1]), "=r"(r[2]), "=r"(r[3]) : "r"(addr));
}
__device__ __forceinline__ void ldsm4t(uint32_t* r, uint32_t addr)
{
    asm volatile("ldmatrix.sync.aligned.m8n8.x4.trans.shared.b16 {%0,%1,%2,%3}, [%4];"
                 : "=r"(r[0]), "=r"(r[1]), "=r"(r[2]), "=r"(r[3]) : "r"(addr));
}

// fp16 mma
__device__ __forceinline__ void mma16816h(float* c, const uint32_t* a,
                                          uint32_t b0, uint32_t b1)
{
    asm volatile("mma.sync.aligned.m16n8k16.row.col.f32.f16.f16.f32 "
                 "{%0,%1,%2,%3}, {%4,%5,%6,%7}, {%8,%9}, {%0,%1,%2,%3};"
                 : "+f"(c[0]), "+f"(c[1]), "+f"(c[2]), "+f"(c[3])
                 : "r"(a[0]), "r"(a[1]), "r"(a[2]), "r"(a[3]), "r"(b0), "r"(b1));
}

// SMEM tile: 128 rows x 128 half-words (256 B/row = 16 chunks of 16 B).
// chunk' = chunk ^ (row&7): conflict-free ldmatrix on all patterns.
__device__ __forceinline__ uint32_t sw_off(int row, int chunk)
{
    return (uint32_t)((row << 8) + ((chunk ^ (row & 7)) << 4));
}

#define CPA16(dst, src) \
    asm volatile("cp.async.cg.shared.global [%0], [%1], 16;" \
                 :: "r"(dst), "l"(src) : "memory")
#define CPA_COMMIT() asm volatile("cp.async.commit_group;" ::: "memory")
#define CPA_WAIT(n)  asm volatile("cp.async.wait_group %0;" :: "n"(n) : "memory")

// ---------------------------------------------------------------------------
// Kernel 0: compute LPT permutation (batches sorted by sen_len descending).
// ---------------------------------------------------------------------------
__global__ void perm_kernel(const int* __restrict__ sen_len)
{
    if (threadIdx.x == 0) {
        int len[B_], idx[B_];
        #pragma unroll
        for (int i = 0; i < B_; i++) { len[i] = sen_len[i]; idx[i] = i; }
        for (int i = 0; i < B_ - 1; i++) {
            int m = i;
            for (int j = i + 1; j < B_; j++) if (len[j] > len[m]) m = j;
            int t = len[i]; len[i] = len[m]; len[m] = t;
            t = idx[i]; idx[i] = idx[m]; idx[m] = t;
        }
        #pragma unroll
        for (int i = 0; i < B_; i++) g_perm[i] = idx[i];
    }
}

// ---------------------------------------------------------------------------
// Kernel 1: QKV projection, 512 threads = 16 warps, fp16 2-pass internals.
// K/V tiles beyond sen_len[b] are never read by attention -> early exit.
// Emits pre-swizzled fp16 hi/lo tiles; Q pre-scaled by 1/16; Q-lo skipped.
// ---------------------------------------------------------------------------
#define QAH 0
#define QWH 32768
#define QWL 65536
#define QKV_SMEM 98304

__global__ __launch_bounds__(512, 1) void qkv_mma_kernel(
    const float* __restrict__ A,
    const float* __restrict__ Wq,
    const float* __restrict__ Wk,
    const float* __restrict__ Wv,
    const int* __restrict__ sen_len)
{
    const int tile = blockIdx.x;
    const int z    = blockIdx.z;

    // Dead-tile skip: K/V tile ti of batch b is read only if ti*128 < sen_len[b].
    if (z != 0) {
        int bb = tile >> 4, ti = tile & 15;
        if (ti * 128 >= sen_len[bb]) return;
    }

    extern __shared__ char smem[];
    const uint32_t sb = smem_u32(smem);

    const int tid  = threadIdx.x;
    const int wid  = tid >> 5;
    const int ln   = tid & 31;
    const int wq   = wid & 7;
    const int wh   = wid >> 3;
    const int row0 = tile * 128;

    const float* W = (z == 0) ? Wq : (z == 1) ? Wk : Wv;
    uint4* OH = (z == 0) ? g_Qhi : (z == 1) ? g_Khi : g_Vhi;
    uint4* OL = (z == 0) ? (uint4*)nullptr : (z == 1) ? g_Klo : g_Vlo;

    float oacc[8][4];
    #pragma unroll
    for (int nt = 0; nt < 8; nt++)
        #pragma unroll
        for (int j = 0; j < 4; j++) oacc[nt][j] = 0.0f;

    for (int k0 = 0; k0 < DIN_; k0 += 128) {
        if (k0) __syncthreads();
        // Convert A half: rows m 0..127, cols k0..k0+127 -> fp16 hi only.
        #pragma unroll
        for (int it = 0; it < 4; it++) {
            int idx = tid + it * 512;
            int r = idx >> 4, ch = idx & 15;
            const float4* src = (const float4*)&A[(size_t)(row0 + r) * DIN_ + k0 + ch * 8];
            float4 v0 = src[0], v1 = src[1];
            uint32_t h0 = packh(v0.x, v0.y);
            uint32_t h1 = packh(v0.z, v0.w);
            uint32_t h2 = packh(v1.x, v1.y);
            uint32_t h3 = packh(v1.z, v1.w);
            *(uint4*)(smem + QAH + sw_off(r, ch)) = make_uint4(h0, h1, h2, h3);
        }
        // Convert W half: rows k k0..k0+127, cols n 0..127 -> fp16 hi/lo.
        #pragma unroll
        for (int it = 0; it < 4; it++) {
            int idx = tid + it * 512;
            int r = idx >> 4, ch = idx & 15;
            const float4* src = (const float4*)&W[(size_t)(k0 + r) * DATT_ + ch * 8];
            float4 v0 = src[0], v1 = src[1];
            uint32_t h[4], l[4];
            split2h(v0.x, v0.y, h[0], l[0]);
            split2h(v0.z, v0.w, h[1], l[1]);
            split2h(v1.x, v1.y, h[2], l[2]);
            split2h(v1.z, v1.w, h[3], l[3]);
            uint32_t a = sw_off(r, ch);
            *(uint4*)(smem + QWH + a) = make_uint4(h[0], h[1], h[2], h[3]);
            *(uint4*)(smem + QWL + a) = make_uint4(l[0], l[1], l[2], l[3]);
        }
        __syncthreads();

        // O += Ahi (Whi + Wlo) : 2-pass fp16.
        #pragma unroll
        for (int kk = 0; kk < 8; kk++) {
            uint32_t ahi[4];
            ldsm4(ahi, sb + QAH + sw_off(wq * 16 + (ln & 15), kk * 2 + (ln >> 4)));
            #pragma unroll
            for (int nd2 = 0; nd2 < 4; nd2++) {
                int krow = kk * 16 + (ln & 7) + (ln & 8);
                int chnk = wh * 8 + nd2 * 2 + ((ln >> 4) & 1);
                uint32_t woff = sw_off(krow, chnk);
                uint32_t wh_[4], wl_[4];
                ldsm4t(wh_, sb + QWH + woff);
                ldsm4t(wl_, sb + QWL + woff);
                mma16816h(oacc[2 * nd2],     ahi, wh_[0], wh_[1]);
                mma16816h(oacc[2 * nd2 + 1], ahi, wh_[2], wh_[3]);
                mma16816h(oacc[2 * nd2],     ahi, wl_[0], wl_[1]);
                mma16816h(oacc[2 * nd2 + 1], ahi, wl_[2], wl_[3]);
            }
        }
    }
    __syncthreads();

    // Stage accumulators to fp32 smem (stride 130), then split to global.
    float* stg = (float*)smem;
    const float scale = (z == 0) ? 0.0625f : 1.0f;
    {
        const int r  = wq * 16 + (ln >> 2);
        const int c0 = wh * 64 + 2 * (ln & 3);
        #pragma unroll
        for (int nt = 0; nt < 8; nt++) {
            int c = c0 + nt * 8;
            stg[r * 130 + c]           = oacc[nt][0] * scale;
            stg[r * 130 + c + 1]       = oacc[nt][1] * scale;
            stg[(r + 8) * 130 + c]     = oacc[nt][2] * scale;
            stg[(r + 8) * 130 + c + 1] = oacc[nt][3] * scale;
        }
    }
    __syncthreads();
    #pragma unroll
    for (int it = 0; it < 4; it++) {
        int idx = tid + it * 512;
        int r = idx >> 4, ch = idx & 15;
        const float* p = &stg[r * 130 + ch * 8];
        uint32_t h[4], l[4];
        split2h(p[0], p[1], h[0], l[0]);
        split2h(p[2], p[3], h[1], l[1]);
        split2h(p[4], p[5], h[2], l[2]);
        split2h(p[6], p[7], h[3], l[3]);
        size_t cidx = (size_t)tile * 2048 + (sw_off(r, ch) >> 4);
        OH[cidx] = make_uint4(h[0], h[1], h[2], h[3]);
        if (OL) OL[cidx] = make_uint4(l[0], l[1], l[2], l[3]);
    }
}

// ---------------------------------------------------------------------------
// Kernel 2: mma.sync fp16 2-pass flash attention, LPT-ordered 1-D grid:
// block bid -> batch g_perm[bid>>4], q-tile (bid&15). Longest batches are
// dispatched first; the tail fills with short jobs.
// 256 threads, 8 warps x 16 q-rows, pipelined K/V prefetch.
// ---------------------------------------------------------------------------
#define SMQH 0
#define SMKH 32768
#define SMKL 65536
#define SMVH 98304
#define SMVL 131072
#define ATTN_SMEM 163840

__global__ __launch_bounds__(256, 1) void attn_mma_kernel(
    const int* __restrict__ sen_len,
    float* __restrict__ out)
{
    extern __shared__ char smem[];
    const uint32_t sb = smem_u32(smem);

    const int tid = threadIdx.x;
    const int wid = tid >> 5;
    const int ln  = tid & 31;
    const int bid = blockIdx.x;
    const int b   = g_perm[bid >> 4];        // LPT: longest batches first
    const int qt  = bid & 15;
    const int q0  = qt * 128;
    const int L   = sen_len[b];
    const int ntiles = (L + 127) >> 7;
    const size_t tb0 = (size_t)(b * 16) * 2048;

    // ---- Prologue: group[Q+K0], group[V0] ----
    {
        const uint4* QH = g_Qhi + tb0 + (size_t)qt * 2048;
        #pragma unroll
        for (int it = 0; it < 8; it++) {
            int c = tid + it * 256;
            CPA16(sb + SMQH + c * 16, QH + c);
            CPA16(sb + SMKH + c * 16, g_Khi + tb0 + c);
            CPA16(sb + SMKL + c * 16, g_Klo + tb0 + c);
        }
        CPA_COMMIT();
        #pragma unroll
        for (int it = 0; it < 8; it++) {
            int c = tid + it * 256;
            CPA16(sb + SMVH + c * 16, g_Vhi + tb0 + c);
            CPA16(sb + SMVL + c * 16, g_Vlo + tb0 + c);
        }
        CPA_COMMIT();
    }

    const int q0w = wid * 16;
    float oacc[16][4];
    #pragma unroll
    for (int nt = 0; nt < 16; nt++)
        #pragma unroll
        for (int j = 0; j < 4; j++) oacc[nt][j] = 0.0f;
    float lsum0 = 0.0f, lsum1 = 0.0f;

    for (int t = 0; t < ntiles; t++) {
        CPA_WAIT(1);        // Q+K(t) ready; V(t) may fly
        __syncthreads();

        // ---- S = Qhi (Khi + Klo)^T : 2-pass fp16, pair-interleaved ----
        float sacc[16][4];
        #pragma unroll
        for (int nt = 0; nt < 16; nt++)
            #pragma unroll
            for (int j = 0; j < 4; j++) sacc[nt][j] = 0.0f;

        const int keyb = (ln & 7) + ((ln & 16) >> 1);

        #pragma unroll
        for (int kk = 0; kk < 8; kk++) {
            const int chnk = kk * 2 + ((ln & 8) >> 3);
            uint32_t ahi[4];
            ldsm4(ahi, sb + SMQH + sw_off(q0w + (ln & 15), kk * 2 + (ln >> 4)));

            uint32_t bh[2][2][4], bl[2][2][4];   // [buf][key-of-pair][frag]
            ldsm4(bh[0][0], sb + SMKH + sw_off(keyb,      chnk));
            ldsm4(bl[0][0], sb + SMKL + sw_off(keyb,      chnk));
            ldsm4(bh[0][1], sb + SMKH + sw_off(keyb + 16, chnk));
            ldsm4(bl[0][1], sb + SMKL + sw_off(keyb + 16, chnk));

            #pragma unroll
            for (int p = 0; p < 4; p++) {
                const int cur = p & 1, nxt = cur ^ 1;
                if (p < 3) {
                    int ky = keyb + (p + 1) * 32;
                    ldsm4(bh[nxt][0], sb + SMKH + sw_off(ky,      chnk));
                    ldsm4(bl[nxt][0], sb + SMKL + sw_off(ky,      chnk));
                    ldsm4(bh[nxt][1], sb + SMKH + sw_off(ky + 16, chnk));
                    ldsm4(bl[nxt][1], sb + SMKL + sw_off(ky + 16, chnk));
                }
                float* s0 = sacc[4 * p];
                float* s1 = sacc[4 * p + 1];
                float* s2 = sacc[4 * p + 2];
                float* s3 = sacc[4 * p + 3];
                mma16816h(s0, ahi, bh[cur][0][0], bh[cur][0][1]);
                mma16816h(s1, ahi, bh[cur][0][2], bh[cur][0][3]);
                mma16816h(s2, ahi, bh[cur][1][0], bh[cur][1][1]);
                mma16816h(s3, ahi, bh[cur][1][2], bh[cur][1][3]);
                mma16816h(s0, ahi, bl[cur][0][0], bl[cur][0][1]);
                mma16816h(s1, ahi, bl[cur][0][2], bl[cur][0][3]);
                mma16816h(s2, ahi, bl[cur][1][0], bl[cur][1][1]);
                mma16816h(s3, ahi, bl[cur][1][2], bl[cur][1][3]);
            }
        }

        // ---- sK dead: prefetch K(t+1) (empty group on last tile) ----
        __syncthreads();
        if (t + 1 < ntiles) {
            const size_t tb = tb0 + (size_t)(t + 1) * 2048;
            #pragma unroll
            for (int it = 0; it < 8; it++) {
                int c = tid + it * 256;
                CPA16(sb + SMKH + c * 16, g_Khi + tb + c);
                CPA16(sb + SMKL + c * 16, g_Klo + tb + c);
            }
        }
        CPA_COMMIT();

        // ---- Softmax (registers only; P kept as fp16 hi only) ----
        uint32_t phi[8][4];
        const int kb = t * 128 + 2 * (ln & 3);
        #pragma unroll
        for (int nt = 0; nt < 16; nt++) {
            int kcol = kb + nt * 8;
            float p0 = (kcol     < L) ? __expf(sacc[nt][0]) : 0.f;
            float p1 = (kcol + 1 < L) ? __expf(sacc[nt][1]) : 0.f;
            float p2 = (kcol     < L) ? __expf(sacc[nt][2]) : 0.f;
            float p3 = (kcol + 1 < L) ? __expf(sacc[nt][3]) : 0.f;
            lsum0 += p0 + p1;
            lsum1 += p2 + p3;
            phi[nt >> 1][(nt & 1) * 2]     = packh(p0, p1);
            phi[nt >> 1][(nt & 1) * 2 + 1] = packh(p2, p3);
        }

        CPA_WAIT(1);        // V(t) ready (K(t+1) in flight)
        __syncthreads();

        // ---- O += Phi (Vhi + Vlo) : 2-pass fp16, pair-interleaved ----
        const int keyr0 = (ln & 7) + (ln & 8);
        #pragma unroll
        for (int kk = 0; kk < 8; kk++) {
            const int keyr = kk * 16 + keyr0;
            const int ch0  = (ln >> 4) & 1;

            uint32_t vh[2][2][4], vl[2][2][4];   // [buf][d-of-pair][frag]
            ldsm4t(vh[0][0], sb + SMVH + sw_off(keyr, ch0));
            ldsm4t(vl[0][0], sb + SMVL + sw_off(keyr, ch0));
            ldsm4t(vh[0][1], sb + SMVH + sw_off(keyr, ch0 + 2));
            ldsm4t(vl[0][1], sb + SMVL + sw_off(keyr, ch0 + 2));

            #pragma unroll
            for (int p = 0; p < 4; p++) {
                const int cur = p & 1, nxt = cur ^ 1;
                if (p < 3) {
                    int ch = ch0 + (p + 1) * 4;
                    ldsm4t(vh[nxt][0], sb + SMVH + sw_off(keyr, ch));
                    ldsm4t(vl[nxt][0], sb + SMVL + sw_off(keyr, ch));
                    ldsm4t(vh[nxt][1], sb + SMVH + sw_off(keyr, ch + 2));
                    ldsm4t(vl[nxt][1], sb + SMVL + sw_off(keyr, ch + 2));
                }
                float* o0 = oacc[4 * p];
                float* o1 = oacc[4 * p + 1];
                float* o2 = oacc[4 * p + 2];
                float* o3 = oacc[4 * p + 3];
                mma16816h(o0, phi[kk], vh[cur][0][0], vh[cur][0][1]);
                mma16816h(o1, phi[kk], vh[cur][0][2], vh[cur][0][3]);
                mma16816h(o2, phi[kk], vh[cur][1][0], vh[cur][1][1]);
                mma16816h(o3, phi[kk], vh[cur][1][2], vh[cur][1][3]);
                mma16816h(o0, phi[kk], vl[cur][0][0], vl[cur][0][1]);
                mma16816h(o1, phi[kk], vl[cur][0][2], vl[cur][0][3]);
                mma16816h(o2, phi[kk], vl[cur][1][0], vl[cur][1][1]);
                mma16816h(o3, phi[kk], vl[cur][1][2], vl[cur][1][3]);
            }
        }

        // ---- sV dead: prefetch V(t+1) (empty group on last tile) ----
        __syncthreads();
        if (t + 1 < ntiles) {
            const size_t tb = tb0 + (size_t)(t + 1) * 2048;
            #pragma unroll
            for (int it = 0; it < 8; it++) {
                int c = tid + it * 256;
                CPA16(sb + SMVH + c * 16, g_Vhi + tb + c);
                CPA16(sb + SMVL + c * 16, g_Vlo + tb + c);
            }
        }
        CPA_COMMIT();
    }
    CPA_WAIT(0);   // drain trailing empty groups

    // ---- Epilogue ----
    #pragma unroll
    for (int off = 1; off < 4; off <<= 1) {
        lsum0 += __shfl_xor_sync(0xffffffffu, lsum0, off);
        lsum1 += __shfl_xor_sync(0xffffffffu, lsum1, off);
    }
    const float inv0 = 1.0f / lsum0;
    const float inv1 = 1.0f / lsum1;

    const int g    = ln >> 2;
    const int tid4 = ln & 3;
    const int row  = q0 + q0w + g;
    float* o0 = &out[((size_t)b * S_ + row) * DATT_];
    float* o1 = &out[((size_t)b * S_ + row + 8) * DATT_];
    #pragma unroll
    for (int nt = 0; nt < 16; nt++) {
        int c = nt * 8 + 2 * tid4;
        *(float2*)(o0 + c) = make_float2(oacc[nt][0] * inv0, oacc[nt][1] * inv0);
        *(float2*)(o1 + c) = make_float2(oacc[nt][2] * inv1, oacc[nt][3] * inv1);
    }
}

// ---------------------------------------------------------------------------
extern "C" void kernel_launch(void* const* d_in, const int* in_sizes, int n_in,
                              void* d_out, int out_size)
{
    (void)in_sizes; (void)n_in; (void)out_size;
    const float* inputs  = (const float*)d_in[0];
    const int*   sen_len = (const int*)  d_in[1];
    const float* Wq      = (const float*)d_in[2];
    const float* Wk      = (const float*)d_in[3];
    const float* Wv      = (const float*)d_in[4];
    float* out = (float*)d_out;

    perm_kernel<<<1, 32>>>(sen_len);

    cudaFuncSetAttribute(qkv_mma_kernel,
                         cudaFuncAttributeMaxDynamicSharedMemorySize, QKV_SMEM);
    qkv_mma_kernel<<<dim3(NTILE, 1, 3), 512, QKV_SMEM>>>(inputs, Wq, Wk, Wv, sen_len);

    cudaFuncSetAttribute(attn_mma_kernel,
                         cudaFuncAttributeMaxDynamicSharedMemorySize, ATTN_SMEM);
    attn_mma_kernel<<<NTILE, 256, ATTN_SMEM>>>(sen_len, out);
}

// round 16
// speedup vs baseline: 1.9016x; 1.0092x over previous
#include <cuda_runtime.h>
#include <cuda_bf16.h>
#include <cuda_fp16.h>
#include <cstdint>
#include <cstddef>

#define B_    16
#define S_    2048
#define DIN_  256
#define DATT_ 128
#define NTILE ((B_ * S_) / 128)   // 256 row-tiles of 128

// Pre-swizzled fp16 hi/lo tiles (16B chunks). Tile t = flattened rows
// [t*128, (t+1)*128) of [B*S, 128]; within a tile, chunk index = sw_off>>4.
__device__ uint4 g_Qhi[(size_t)NTILE * 2048];
__device__ uint4 g_Khi[(size_t)NTILE * 2048];
__device__ uint4 g_Klo[(size_t)NTILE * 2048];
__device__ uint4 g_Vhi[(size_t)NTILE * 2048];
__device__ uint4 g_Vlo[(size_t)NTILE * 2048];

// Pre-swizzled fp16-hi W half-tiles: index (z*2 + half)*2048 + chunk.
__device__ uint4 g_Wh[6 * 2048];

// LPT batch order (sorted by sen_len descending).
__device__ int g_perm[B_];

// ---------------------------------------------------------------------------
// Helpers
// ---------------------------------------------------------------------------
__device__ __forceinline__ uint32_t smem_u32(const void* p) {
    uint32_t a;
    asm("{ .reg .u64 t; cvta.to.shared.u64 t, %1; cvt.u32.u64 %0, t; }"
        : "=r"(a) : "l"(p));
    return a;
}

// fp16 split (10-bit mantissa -> lo term ~2^-12 relative coverage to 2^-22).
__device__ __forceinline__ void split2h(float a, float b, uint32_t& hi, uint32_t& lo)
{
    __half ah = __float2half_rn(a), bh = __float2half_rn(b);
    float ar = a - __half2float(ah), br = b - __half2float(bh);
    __half al = __float2half_rn(ar), bl = __float2half_rn(br);
    hi = (uint32_t)__half_as_ushort(ah) | ((uint32_t)__half_as_ushort(bh) << 16);
    lo = (uint32_t)__half_as_ushort(al) | ((uint32_t)__half_as_ushort(bl) << 16);
}

// Pack two fp32 -> fp16x2 (a -> low half).
__device__ __forceinline__ uint32_t packh(float a, float b)
{
    return (uint32_t)__half_as_ushort(__float2half_rn(a))
         | ((uint32_t)__half_as_ushort(__float2half_rn(b)) << 16);
}

__device__ __forceinline__ void ldsm4(uint32_t* r, uint32_t addr)
{
    asm volatile("ldmatrix.sync.aligned.m8n8.x4.shared.b16 {%0,%1,%2,%3}, [%4];"
                 : "=r"(r[0]), "=r"(r[1]), "=r"(r[2]), "=r"(r[3]) : "r"(addr));
}
__device__ __forceinline__ void ldsm4t(uint32_t* r, uint32_t addr)
{
    asm volatile("ldmatrix.sync.aligned.m8n8.x4.trans.shared.b16 {%0,%1,%2,%3}, [%4];"
                 : "=r"(r[0]), "=r"(r[1]), "=r"(r[2]), "=r"(r[3]) : "r"(addr));
}

// fp16 mma
__device__ __forceinline__ void mma16816h(float* c, const uint32_t* a,
                                          uint32_t b0, uint32_t b1)
{
    asm volatile("mma.sync.aligned.m16n8k16.row.col.f32.f16.f16.f32 "
                 "{%0,%1,%2,%3}, {%4,%5,%6,%7}, {%8,%9}, {%0,%1,%2,%3};"
                 : "+f"(c[0]), "+f"(c[1]), "+f"(c[2]), "+f"(c[3])
                 : "r"(a[0]), "r"(a[1]), "r"(a[2]), "r"(a[3]), "r"(b0), "r"(b1));
}

// SMEM tile: 128 rows x 128 half-words (256 B/row = 16 chunks of 16 B).
// chunk' = chunk ^ (row&7): conflict-free ldmatrix on all patterns.
__device__ __forceinline__ uint32_t sw_off(int row, int chunk)
{
    return (uint32_t)((row << 8) + ((chunk ^ (row & 7)) << 4));
}

#define CPA16(dst, src) \
    asm volatile("cp.async.cg.shared.global [%0], [%1], 16;" \
                 :: "r"(dst), "l"(src) : "memory")
#define CPA_COMMIT() asm volatile("cp.async.commit_group;" ::: "memory")
#define CPA_WAIT(n)  asm volatile("cp.async.wait_group %0;" :: "n"(n) : "memory")

// ---------------------------------------------------------------------------
// Kernel 0: setup — convert W to pre-swizzled fp16-hi half-tiles + LPT perm.
// grid = 6 blocks (z*2+half) x 256 threads.
// ---------------------------------------------------------------------------
__global__ void setup_kernel(const float* __restrict__ Wq,
                             const float* __restrict__ Wk,
                             const float* __restrict__ Wv,
                             const int* __restrict__ sen_len)
{
    const int i = blockIdx.x;      // 0..5
    const int z = i >> 1, h = i & 1;
    const float* W = (z == 0) ? Wq : (z == 1) ? Wk : Wv;
    const int tid = threadIdx.x;
    #pragma unroll
    for (int it = 0; it < 8; it++) {
        int idx = tid + it * 256;
        int r = idx >> 4, ch = idx & 15;
        const float4* src = (const float4*)&W[(size_t)(h * 128 + r) * DATT_ + ch * 8];
        float4 v0 = src[0], v1 = src[1];
        uint4 out;
        out.x = packh(v0.x, v0.y);
        out.y = packh(v0.z, v0.w);
        out.z = packh(v1.x, v1.y);
        out.w = packh(v1.z, v1.w);
        g_Wh[i * 2048 + (sw_off(r, ch) >> 4)] = out;
    }
    if (i == 0 && tid == 0) {
        int len[B_], idx[B_];
        #pragma unroll
        for (int k = 0; k < B_; k++) { len[k] = sen_len[k]; idx[k] = k; }
        for (int k = 0; k < B_ - 1; k++) {
            int m = k;
            for (int j = k + 1; j < B_; j++) if (len[j] > len[m]) m = j;
            int t = len[k]; len[k] = len[m]; len[m] = t;
            t = idx[k]; idx[k] = idx[m]; idx[m] = t;
        }
        #pragma unroll
        for (int k = 0; k < B_; k++) g_perm[k] = idx[k];
    }
}

// ---------------------------------------------------------------------------
// Kernel 1: fused QKV projection. 256 blocks (one per row-tile), 512 threads.
// A converted ONCE per tile (fp16 hi/lo, both K-halves resident, 128 KB);
// W-hi streamed via double-buffered cp.async (chunks of one 32 KB half-tile).
// Dropped term is A*W-lo (W-hi only) — same ~2^-12 magnitude as before.
// K/V outputs skipped for tiles beyond sen_len. Q pre-scaled 1/16, Q-lo none.
// Epilogue stages fp16 in the just-freed W buffer (row stride 256 B — the
// 128-col fp16 row occupies exactly 256 B; 128 rows fill the 32 KB buffer).
// ---------------------------------------------------------------------------
#define FWB     131072     // W buffers: 32 KB each at FWB + (ci&1)*32768
#define QKV_SMEM 196608

__global__ __launch_bounds__(512, 1) void qkv_fused_kernel(
    const float* __restrict__ A,
    const int* __restrict__ sen_len)
{
    extern __shared__ char smem[];
    const uint32_t sb = smem_u32(smem);

    const int tid  = threadIdx.x;
    const int wid  = tid >> 5;
    const int ln   = tid & 31;
    const int wq   = wid & 7;
    const int wh   = wid >> 3;
    const int tile = blockIdx.x;
    const int row0 = tile * 128;
    const bool alive = ((tile & 15) * 128) < sen_len[tile >> 4];
    const int nc = alive ? 6 : 2;   // chunks: (z,half) pairs

    // Prefetch W chunks 0 and 1 first (overlaps with A conversion).
    #pragma unroll
    for (int it = 0; it < 4; it++) {
        int c = tid + it * 512;
        CPA16(sb + FWB + c * 16, g_Wh + c);
    }
    CPA_COMMIT();
    #pragma unroll
    for (int it = 0; it < 4; it++) {
        int c = tid + it * 512;
        CPA16(sb + FWB + 32768 + c * 16, g_Wh + 2048 + c);
    }
    CPA_COMMIT();

    // Convert A: both K-halves, fp16 hi+lo.
    #pragma unroll
    for (int it = 0; it < 8; it++) {
        int idx = tid + it * 512;       // 0..4095
        int hh  = idx >> 11;            // K-half
        int sub = idx & 2047;
        int r = sub >> 4, ch = sub & 15;
        const float4* src = (const float4*)&A[(size_t)(row0 + r) * DIN_ + hh * 128 + ch * 8];
        float4 v0 = src[0], v1 = src[1];
        uint32_t hx[4], lx[4];
        split2h(v0.x, v0.y, hx[0], lx[0]);
        split2h(v0.z, v0.w, hx[1], lx[1]);
        split2h(v1.x, v1.y, hx[2], lx[2]);
        split2h(v1.z, v1.w, hx[3], lx[3]);
        uint32_t a = sw_off(r, ch);
        *(uint4*)(smem + hh * 65536 + a)         = make_uint4(hx[0], hx[1], hx[2], hx[3]);
        *(uint4*)(smem + hh * 65536 + 32768 + a) = make_uint4(lx[0], lx[1], lx[2], lx[3]);
    }

    float oacc[8][4];

    for (int ci = 0; ci < nc; ci++) {
        const int z  = ci >> 1;
        const int hh = ci & 1;
        const uint32_t wboff = FWB + (uint32_t)(ci & 1) * 32768;

        if (hh == 0) {
            #pragma unroll
            for (int nt = 0; nt < 8; nt++)
                #pragma unroll
                for (int j = 0; j < 4; j++) oacc[nt][j] = 0.0f;
        }

        CPA_WAIT(1);        // chunk ci landed (newest = ci+1 may fly)
        __syncthreads();

        // O += (Ahi + Alo)[half hh] * Whi : 2-pass fp16.
        const uint32_t ah_base = sb + (uint32_t)hh * 65536;
        const uint32_t al_base = ah_base + 32768;
        #pragma unroll
        for (int kk = 0; kk < 8; kk++) {
            uint32_t aoff = sw_off(wq * 16 + (ln & 15), kk * 2 + (ln >> 4));
            uint32_t ahi[4], alo[4];
            ldsm4(ahi, ah_base + aoff);
            ldsm4(alo, al_base + aoff);
            #pragma unroll
            for (int nd2 = 0; nd2 < 4; nd2++) {
                int krow = kk * 16 + (ln & 7) + (ln & 8);
                int chnk = wh * 8 + nd2 * 2 + ((ln >> 4) & 1);
                uint32_t wf[4];
                ldsm4t(wf, sb + wboff + sw_off(krow, chnk));
                mma16816h(oacc[2 * nd2],     ahi, wf[0], wf[1]);
                mma16816h(oacc[2 * nd2 + 1], ahi, wf[2], wf[3]);
                mma16816h(oacc[2 * nd2],     alo, wf[0], wf[1]);
                mma16816h(oacc[2 * nd2 + 1], alo, wf[2], wf[3]);
            }
        }
        __syncthreads();    // all MMA reads of this W buffer done

        if (hh == 1) {
            // Epilogue for z: stage fp16 in the freed W buffer, stride 256 B.
            uint4* OH = (z == 0) ? g_Qhi : (z == 1) ? g_Khi : g_Vhi;
            uint4* OL = (z == 0) ? (uint4*)nullptr : (z == 1) ? g_Klo : g_Vlo;
            const float scale = (z == 0) ? 0.0625f : 1.0f;
            const int r0 = wq * 16 + (ln >> 2);
            const int p0 = wh * 32 + (ln & 3);   // fp16x2 word index in row

            // pass 1: hi halves
            #pragma unroll
            for (int nt = 0; nt < 8; nt++) {
                int pi = p0 + nt * 4;
                *(uint32_t*)(smem + wboff + r0 * 256 + pi * 4) =
                    packh(oacc[nt][0] * scale, oacc[nt][1] * scale);
                *(uint32_t*)(smem + wboff + (r0 + 8) * 256 + pi * 4) =
                    packh(oacc[nt][2] * scale, oacc[nt][3] * scale);
            }
            __syncthreads();
            #pragma unroll
            for (int it = 0; it < 4; it++) {
                int idx = tid + it * 512;
                int r = idx >> 4, ch = idx & 15;
                uint4 v = *(uint4*)(smem + wboff + r * 256 + ch * 16);
                OH[(size_t)tile * 2048 + (sw_off(r, ch) >> 4)] = v;
            }
            __syncthreads();

            if (OL) {
                // pass 2: lo halves (recompute split)
                #pragma unroll
                for (int nt = 0; nt < 8; nt++) {
                    int pi = p0 + nt * 4;
                    uint32_t hx, lx;
                    split2h(oacc[nt][0] * scale, oacc[nt][1] * scale, hx, lx);
                    *(uint32_t*)(smem + wboff + r0 * 256 + pi * 4) = lx;
                    split2h(oacc[nt][2] * scale, oacc[nt][3] * scale, hx, lx);
                    *(uint32_t*)(smem + wboff + (r0 + 8) * 256 + pi * 4) = lx;
                }
                __syncthreads();
                #pragma unroll
                for (int it = 0; it < 4; it++) {
                    int idx = tid + it * 512;
                    int r = idx >> 4, ch = idx & 15;
                    uint4 v = *(uint4*)(smem + wboff + r * 256 + ch * 16);
                    OL[(size_t)tile * 2048 + (sw_off(r, ch) >> 4)] = v;
                }
                __syncthreads();
            }
        }

        // Prefetch chunk ci+2 into this (now fully free) buffer.
        if (ci + 2 < nc) {
            const uint4* src = g_Wh + (size_t)(ci + 2) * 2048;
            #pragma unroll
            for (int it = 0; it < 4; it++) {
                int c = tid + it * 512;
                CPA16(sb + wboff + c * 16, src + c);
            }
        }
        CPA_COMMIT();
    }
    CPA_WAIT(0);
}

// ---------------------------------------------------------------------------
// Kernel 2: mma.sync fp16 2-pass flash attention, LPT-ordered 1-D grid.
// Mask hoist: only the boundary tile pays the predicate/select path.
// 256 threads, 8 warps x 16 q-rows, pipelined K/V prefetch.
// ---------------------------------------------------------------------------
#define SMQH 0
#define SMKH 32768
#define SMKL 65536
#define SMVH 98304
#define SMVL 131072
#define ATTN_SMEM 163840

__global__ __launch_bounds__(256, 1) void attn_mma_kernel(
    const int* __restrict__ sen_len,
    float* __restrict__ out)
{
    extern __shared__ char smem[];
    const uint32_t sb = smem_u32(smem);

    const int tid = threadIdx.x;
    const int wid = tid >> 5;
    const int ln  = tid & 31;
    const int bid = blockIdx.x;
    const int b   = g_perm[bid >> 4];        // LPT: longest batches first
    const int qt  = bid & 15;
    const int q0  = qt * 128;
    const int L   = sen_len[b];
    const int ntiles = (L + 127) >> 7;
    const size_t tb0 = (size_t)(b * 16) * 2048;

    // ---- Prologue: group[Q+K0], group[V0] ----
    {
        const uint4* QH = g_Qhi + tb0 + (size_t)qt * 2048;
        #pragma unroll
        for (int it = 0; it < 8; it++) {
            int c = tid + it * 256;
            CPA16(sb + SMQH + c * 16, QH + c);
            CPA16(sb + SMKH + c * 16, g_Khi + tb0 + c);
            CPA16(sb + SMKL + c * 16, g_Klo + tb0 + c);
        }
        CPA_COMMIT();
        #pragma unroll
        for (int it = 0; it < 8; it++) {
            int c = tid + it * 256;
            CPA16(sb + SMVH + c * 16, g_Vhi + tb0 + c);
            CPA16(sb + SMVL + c * 16, g_Vlo + tb0 + c);
        }
        CPA_COMMIT();
    }

    const int q0w = wid * 16;
    float oacc[16][4];
    #pragma unroll
    for (int nt = 0; nt < 16; nt++)
        #pragma unroll
        for (int j = 0; j < 4; j++) oacc[nt][j] = 0.0f;
    float lsum0 = 0.0f, lsum1 = 0.0f;

    for (int t = 0; t < ntiles; t++) {
        CPA_WAIT(1);        // Q+K(t) ready; V(t) may fly
        __syncthreads();

        // ---- S = Qhi (Khi + Klo)^T : 2-pass fp16, pair-interleaved ----
        float sacc[16][4];
        #pragma unroll
        for (int nt = 0; nt < 16; nt++)
            #pragma unroll
            for (int j = 0; j < 4; j++) sacc[nt][j] = 0.0f;

        const int keyb = (ln & 7) + ((ln & 16) >> 1);

        #pragma unroll
        for (int kk = 0; kk < 8; kk++) {
            const int chnk = kk * 2 + ((ln & 8) >> 3);
            uint32_t ahi[4];
            ldsm4(ahi, sb + SMQH + sw_off(q0w + (ln & 15), kk * 2 + (ln >> 4)));

            uint32_t bh[2][2][4], bl[2][2][4];   // [buf][key-of-pair][frag]
            ldsm4(bh[0][0], sb + SMKH + sw_off(keyb,      chnk));
            ldsm4(bl[0][0], sb + SMKL + sw_off(keyb,      chnk));
            ldsm4(bh[0][1], sb + SMKH + sw_off(keyb + 16, chnk));
            ldsm4(bl[0][1], sb + SMKL + sw_off(keyb + 16, chnk));

            #pragma unroll
            for (int p = 0; p < 4; p++) {
                const int cur = p & 1, nxt = cur ^ 1;
                if (p < 3) {
                    int ky = keyb + (p + 1) * 32;
                    ldsm4(bh[nxt][0], sb + SMKH + sw_off(ky,      chnk));
                    ldsm4(bl[nxt][0], sb + SMKL + sw_off(ky,      chnk));
                    ldsm4(bh[nxt][1], sb + SMKH + sw_off(ky + 16, chnk));
                    ldsm4(bl[nxt][1], sb + SMKL + sw_off(ky + 16, chnk));
                }
                float* s0 = sacc[4 * p];
                float* s1 = sacc[4 * p + 1];
                float* s2 = sacc[4 * p + 2];
                float* s3 = sacc[4 * p + 3];
                mma16816h(s0, ahi, bh[cur][0][0], bh[cur][0][1]);
                mma16816h(s1, ahi, bh[cur][0][2], bh[cur][0][3]);
                mma16816h(s2, ahi, bh[cur][1][0], bh[cur][1][1]);
                mma16816h(s3, ahi, bh[cur][1][2], bh[cur][1][3]);
                mma16816h(s0, ahi, bl[cur][0][0], bl[cur][0][1]);
                mma16816h(s1, ahi, bl[cur][0][2], bl[cur][0][3]);
                mma16816h(s2, ahi, bl[cur][1][0], bl[cur][1][1]);
                mma16816h(s3, ahi, bl[cur][1][2], bl[cur][1][3]);
            }
        }

        // ---- sK dead: prefetch K(t+1) (empty group on last tile) ----
        __syncthreads();
        if (t + 1 < ntiles) {
            const size_t tb = tb0 + (size_t)(t + 1) * 2048;
            #pragma unroll
            for (int it = 0; it < 8; it++) {
                int c = tid + it * 256;
                CPA16(sb + SMKH + c * 16, g_Khi + tb + c);
                CPA16(sb + SMKL + c * 16, g_Klo + tb + c);
            }
        }
        CPA_COMMIT();

        // ---- Softmax (registers only; P kept as fp16 hi only).
        //      Mask only on the boundary tile. ----
        uint32_t phi[8][4];
        const bool boundary = (t == ntiles - 1) && (L & 127);
        if (!boundary) {
            #pragma unroll
            for (int nt = 0; nt < 16; nt++) {
                float p0 = __expf(sacc[nt][0]);
                float p1 = __expf(sacc[nt][1]);
                float p2 = __expf(sacc[nt][2]);
                float p3 = __expf(sacc[nt][3]);
                lsum0 += p0 + p1;
                lsum1 += p2 + p3;
                phi[nt >> 1][(nt & 1) * 2]     = packh(p0, p1);
                phi[nt >> 1][(nt & 1) * 2 + 1] = packh(p2, p3);
            }
        } else {
            const int kb = t * 128 + 2 * (ln & 3);
            #pragma unroll
            for (int nt = 0; nt < 16; nt++) {
                int kcol = kb + nt * 8;
                float p0 = (kcol     < L) ? __expf(sacc[nt][0]) : 0.f;
                float p1 = (kcol + 1 < L) ? __expf(sacc[nt][1]) : 0.f;
                float p2 = (kcol     < L) ? __expf(sacc[nt][2]) : 0.f;
                float p3 = (kcol + 1 < L) ? __expf(sacc[nt][3]) : 0.f;
                lsum0 += p0 + p1;
                lsum1 += p2 + p3;
                phi[nt >> 1][(nt & 1) * 2]     = packh(p0, p1);
                phi[nt >> 1][(nt & 1) * 2 + 1] = packh(p2, p3);
            }
        }

        CPA_WAIT(1);        // V(t) ready (K(t+1) in flight)
        __syncthreads();

        // ---- O += Phi (Vhi + Vlo) : 2-pass fp16, pair-interleaved ----
        const int keyr0 = (ln & 7) + (ln & 8);
        #pragma unroll
        for (int kk = 0; kk < 8; kk++) {
            const int keyr = kk * 16 + keyr0;
            const int ch0  = (ln >> 4) & 1;

            uint32_t vh[2][2][4], vl[2][2][4];   // [buf][d-of-pair][frag]
            ldsm4t(vh[0][0], sb + SMVH + sw_off(keyr, ch0));
            ldsm4t(vl[0][0], sb + SMVL + sw_off(keyr, ch0));
            ldsm4t(vh[0][1], sb + SMVH + sw_off(keyr, ch0 + 2));
            ldsm4t(vl[0][1], sb + SMVL + sw_off(keyr, ch0 + 2));

            #pragma unroll
            for (int p = 0; p < 4; p++) {
                const int cur = p & 1, nxt = cur ^ 1;
                if (p < 3) {
                    int ch = ch0 + (p + 1) * 4;
                    ldsm4t(vh[nxt][0], sb + SMVH + sw_off(keyr, ch));
                    ldsm4t(vl[nxt][0], sb + SMVL + sw_off(keyr, ch));
                    ldsm4t(vh[nxt][1], sb + SMVH + sw_off(keyr, ch + 2));
                    ldsm4t(vl[nxt][1], sb + SMVL + sw_off(keyr, ch + 2));
                }
                float* o0 = oacc[4 * p];
                float* o1 = oacc[4 * p + 1];
                float* o2 = oacc[4 * p + 2];
                float* o3 = oacc[4 * p + 3];
                mma16816h(o0, phi[kk], vh[cur][0][0], vh[cur][0][1]);
                mma16816h(o1, phi[kk], vh[cur][0][2], vh[cur][0][3]);
                mma16816h(o2, phi[kk], vh[cur][1][0], vh[cur][1][1]);
                mma16816h(o3, phi[kk], vh[cur][1][2], vh[cur][1][3]);
                mma16816h(o0, phi[kk], vl[cur][0][0], vl[cur][0][1]);
                mma16816h(o1, phi[kk], vl[cur][0][2], vl[cur][0][3]);
                mma16816h(o2, phi[kk], vl[cur][1][0], vl[cur][1][1]);
                mma16816h(o3, phi[kk], vl[cur][1][2], vl[cur][1][3]);
            }
        }

        // ---- sV dead: prefetch V(t+1) (empty group on last tile) ----
        __syncthreads();
        if (t + 1 < ntiles) {
            const size_t tb = tb0 + (size_t)(t + 1) * 2048;
            #pragma unroll
            for (int it = 0; it < 8; it++) {
                int c = tid + it * 256;
                CPA16(sb + SMVH + c * 16, g_Vhi + tb + c);
                CPA16(sb + SMVL + c * 16, g_Vlo + tb + c);
            }
        }
        CPA_COMMIT();
    }
    CPA_WAIT(0);   // drain trailing empty groups

    // ---- Epilogue ----
    #pragma unroll
    for (int off = 1; off < 4; off <<= 1) {
        lsum0 += __shfl_xor_sync(0xffffffffu, lsum0, off);
        lsum1 += __shfl_xor_sync(0xffffffffu, lsum1, off);
    }
    const float inv0 = 1.0f / lsum0;
    const float inv1 = 1.0f / lsum1;

    const int g    = ln >> 2;
    const int tid4 = ln & 3;
    const int row  = q0 + q0w + g;
    float* o0 = &out[((size_t)b * S_ + row) * DATT_];
    float* o1 = &out[((size_t)b * S_ + row + 8) * DATT_];
    #pragma unroll
    for (int nt = 0; nt < 16; nt++) {
        int c = nt * 8 + 2 * tid4;
        *(float2*)(o0 + c) = make_float2(oacc[nt][0] * inv0, oacc[nt][1] * inv0);
        *(float2*)(o1 + c) = make_float2(oacc[nt][2] * inv1, oacc[nt][3] * inv1);
    }
}

// ---------------------------------------------------------------------------
extern "C" void kernel_launch(void* const* d_in, const int* in_sizes, int n_in,
                              void* d_out, int out_size)
{
    (void)in_sizes; (void)n_in; (void)out_size;
    const float* inputs  = (const float*)d_in[0];
    const int*   sen_len = (const int*)  d_in[1];
    const float* Wq      = (const float*)d_in[2];
    const float* Wk      = (const float*)d_in[3];
    const float* Wv      = (const float*)d_in[4];
    float* out = (float*)d_out;

    setup_kernel<<<6, 256>>>(Wq, Wk, Wv, sen_len);

    cudaFuncSetAttribute(qkv_fused_kernel,
                         cudaFuncAttributeMaxDynamicSharedMemorySize, QKV_SMEM);
    qkv_fused_kernel<<<NTILE, 512, QKV_SMEM>>>(inputs, sen_len);

    cudaFuncSetAttribute(attn_mma_kernel,
                         cudaFuncAttributeMaxDynamicSharedMemorySize, ATTN_SMEM);
    attn_mma_kernel<<<NTILE, 256, ATTN_SMEM>>>(sen_len, out);
}

// round 17
// speedup vs baseline: 2.5605x; 1.3465x over previous
#include <cuda_runtime.h>
#include <cuda_bf16.h>
#include <cuda_fp16.h>
#include <cstdint>
#include <cstddef>

#define B_    16
#define S_    2048
#define DIN_  256
#define DATT_ 128
#define NTILE ((B_ * S_) / 128)   // 256 row-tiles of 128

// Pre-swizzled fp16-hi tiles (16B chunks). Tile t = flattened rows
// [t*128, (t+1)*128) of [B*S, 128]; within a tile, chunk index = sw_off>>4.
__device__ uint4 g_Qhi[(size_t)NTILE * 2048];
__device__ uint4 g_Khi[(size_t)NTILE * 2048];
__device__ uint4 g_Vhi[(size_t)NTILE * 2048];

// Pre-swizzled fp16-hi W half-tiles: index (z*2 + half)*2048 + chunk.
__device__ uint4 g_Wh[6 * 2048];

// LPT batch order (sorted by sen_len descending).
__device__ int g_perm[B_];

// ---------------------------------------------------------------------------
// Helpers
// ---------------------------------------------------------------------------
__device__ __forceinline__ uint32_t smem_u32(const void* p) {
    uint32_t a;
    asm("{ .reg .u64 t; cvta.to.shared.u64 t, %1; cvt.u32.u64 %0, t; }"
        : "=r"(a) : "l"(p));
    return a;
}

// fp16 split (hi + lo covers to ~2^-22; lo term used only inside QKV mma).
__device__ __forceinline__ void split2h(float a, float b, uint32_t& hi, uint32_t& lo)
{
    __half ah = __float2half_rn(a), bh = __float2half_rn(b);
    float ar = a - __half2float(ah), br = b - __half2float(bh);
    __half al = __float2half_rn(ar), bl = __float2half_rn(br);
    hi = (uint32_t)__half_as_ushort(ah) | ((uint32_t)__half_as_ushort(bh) << 16);
    lo = (uint32_t)__half_as_ushort(al) | ((uint32_t)__half_as_ushort(bl) << 16);
}

// Pack two fp32 -> fp16x2 (a -> low half).
__device__ __forceinline__ uint32_t packh(float a, float b)
{
    return (uint32_t)__half_as_ushort(__float2half_rn(a))
         | ((uint32_t)__half_as_ushort(__float2half_rn(b)) << 16);
}

__device__ __forceinline__ void ldsm4(uint32_t* r, uint32_t addr)
{
    asm volatile("ldmatrix.sync.aligned.m8n8.x4.shared.b16 {%0,%1,%2,%3}, [%4];"
                 : "=r"(r[0]), "=r"(r[1]), "=r"(r[2]), "=r"(r[3]) : "r"(addr));
}
__device__ __forceinline__ void ldsm4t(uint32_t* r, uint32_t addr)
{
    asm volatile("ldmatrix.sync.aligned.m8n8.x4.trans.shared.b16 {%0,%1,%2,%3}, [%4];"
                 : "=r"(r[0]), "=r"(r[1]), "=r"(r[2]), "=r"(r[3]) : "r"(addr));
}

// fp16 mma
__device__ __forceinline__ void mma16816h(float* c, const uint32_t* a,
                                          uint32_t b0, uint32_t b1)
{
    asm volatile("mma.sync.aligned.m16n8k16.row.col.f32.f16.f16.f32 "
                 "{%0,%1,%2,%3}, {%4,%5,%6,%7}, {%8,%9}, {%0,%1,%2,%3};"
                 : "+f"(c[0]), "+f"(c[1]), "+f"(c[2]), "+f"(c[3])
                 : "r"(a[0]), "r"(a[1]), "r"(a[2]), "r"(a[3]), "r"(b0), "r"(b1));
}

// SMEM tile: 128 rows x 128 half-words (256 B/row = 16 chunks of 16 B).
// chunk' = chunk ^ (row&7): conflict-free ldmatrix on all patterns.
__device__ __forceinline__ uint32_t sw_off(int row, int chunk)
{
    return (uint32_t)((row << 8) + ((chunk ^ (row & 7)) << 4));
}

#define CPA16(dst, src) \
    asm volatile("cp.async.cg.shared.global [%0], [%1], 16;" \
                 :: "r"(dst), "l"(src) : "memory")
#define CPA_COMMIT() asm volatile("cp.async.commit_group;" ::: "memory")
#define CPA_WAIT(n)  asm volatile("cp.async.wait_group %0;" :: "n"(n) : "memory")

// ---------------------------------------------------------------------------
// Kernel 0: setup — W -> fp16-hi half-tiles (12 blocks for latency) + LPT
// perm (sen_len staged via SMEM, sort on registers).
// ---------------------------------------------------------------------------
__global__ void setup_kernel(const float* __restrict__ Wq,
                             const float* __restrict__ Wk,
                             const float* __restrict__ Wv,
                             const int* __restrict__ sen_len)
{
    __shared__ int slen[B_];
    const int blk  = blockIdx.x;       // 0..11
    const int i    = blk >> 1;         // W half-tile 0..5
    const int part = blk & 1;          // which 64-row slice
    const int z = i >> 1, h = i & 1;
    const float* W = (z == 0) ? Wq : (z == 1) ? Wk : Wv;
    const int tid = threadIdx.x;

    if (blk == 0 && tid < B_) slen[tid] = sen_len[tid];

    #pragma unroll
    for (int it = 0; it < 4; it++) {
        int idx = part * 1024 + tid + it * 256;
        int r = idx >> 4, ch = idx & 15;
        const float4* src = (const float4*)&W[(size_t)(h * 128 + r) * DATT_ + ch * 8];
        float4 v0 = src[0], v1 = src[1];
        uint4 out;
        out.x = packh(v0.x, v0.y);
        out.y = packh(v0.z, v0.w);
        out.z = packh(v1.x, v1.y);
        out.w = packh(v1.z, v1.w);
        g_Wh[i * 2048 + (sw_off(r, ch) >> 4)] = out;
    }

    if (blk == 0) {
        __syncthreads();
        if (tid == 0) {
            int len[B_], idx[B_];
            #pragma unroll
            for (int k = 0; k < B_; k++) { len[k] = slen[k]; idx[k] = k; }
            for (int k = 0; k < B_ - 1; k++) {
                int m = k;
                for (int j = k + 1; j < B_; j++) if (len[j] > len[m]) m = j;
                int t = len[k]; len[k] = len[m]; len[m] = t;
                t = idx[k]; idx[k] = idx[m]; idx[m] = t;
            }
            #pragma unroll
            for (int k = 0; k < B_; k++) g_perm[k] = idx[k];
        }
    }
}

// ---------------------------------------------------------------------------
// Kernel 1: fused QKV projection. 256 blocks (one per row-tile), 512 threads.
// A converted once per tile (fp16 hi/lo, 128 KB resident); W-hi streamed via
// double-buffered cp.async. Compute: (Ahi+Alo)*Whi (2-pass). Outputs fp16-hi
// only (lo never used downstream). K/V chunks skipped beyond sen_len.
// Q pre-scaled 1/16. Epilogue stages fp16 in the freed W buffer (256 B rows).
// ---------------------------------------------------------------------------
#define FWB     131072     // W buffers: 32 KB each at FWB + (ci&1)*32768
#define QKV_SMEM 196608

__global__ __launch_bounds__(512, 1) void qkv_fused_kernel(
    const float* __restrict__ A,
    const int* __restrict__ sen_len)
{
    extern __shared__ char smem[];
    const uint32_t sb = smem_u32(smem);

    const int tid  = threadIdx.x;
    const int wid  = tid >> 5;
    const int ln   = tid & 31;
    const int wq   = wid & 7;
    const int wh   = wid >> 3;
    const int tile = blockIdx.x;
    const int row0 = tile * 128;
    const bool alive = ((tile & 15) * 128) < sen_len[tile >> 4];
    const int nc = alive ? 6 : 2;   // chunks: (z,half) pairs

    // Prefetch W chunks 0 and 1 first (overlaps with A conversion).
    #pragma unroll
    for (int it = 0; it < 4; it++) {
        int c = tid + it * 512;
        CPA16(sb + FWB + c * 16, g_Wh + c);
    }
    CPA_COMMIT();
    #pragma unroll
    for (int it = 0; it < 4; it++) {
        int c = tid + it * 512;
        CPA16(sb + FWB + 32768 + c * 16, g_Wh + 2048 + c);
    }
    CPA_COMMIT();

    // Convert A: both K-halves, fp16 hi+lo.
    #pragma unroll
    for (int it = 0; it < 8; it++) {
        int idx = tid + it * 512;       // 0..4095
        int hh  = idx >> 11;            // K-half
        int sub = idx & 2047;
        int r = sub >> 4, ch = sub & 15;
        const float4* src = (const float4*)&A[(size_t)(row0 + r) * DIN_ + hh * 128 + ch * 8];
        float4 v0 = src[0], v1 = src[1];
        uint32_t hx[4], lx[4];
        split2h(v0.x, v0.y, hx[0], lx[0]);
        split2h(v0.z, v0.w, hx[1], lx[1]);
        split2h(v1.x, v1.y, hx[2], lx[2]);
        split2h(v1.z, v1.w, hx[3], lx[3]);
        uint32_t a = sw_off(r, ch);
        *(uint4*)(smem + hh * 65536 + a)         = make_uint4(hx[0], hx[1], hx[2], hx[3]);
        *(uint4*)(smem + hh * 65536 + 32768 + a) = make_uint4(lx[0], lx[1], lx[2], lx[3]);
    }

    float oacc[8][4];

    for (int ci = 0; ci < nc; ci++) {
        const int z  = ci >> 1;
        const int hh = ci & 1;
        const uint32_t wboff = FWB + (uint32_t)(ci & 1) * 32768;

        if (hh == 0) {
            #pragma unroll
            for (int nt = 0; nt < 8; nt++)
                #pragma unroll
                for (int j = 0; j < 4; j++) oacc[nt][j] = 0.0f;
        }

        CPA_WAIT(1);        // chunk ci landed (newest = ci+1 may fly)
        __syncthreads();

        // O += (Ahi + Alo)[half hh] * Whi : 2-pass fp16.
        const uint32_t ah_base = sb + (uint32_t)hh * 65536;
        const uint32_t al_base = ah_base + 32768;
        #pragma unroll
        for (int kk = 0; kk < 8; kk++) {
            uint32_t aoff = sw_off(wq * 16 + (ln & 15), kk * 2 + (ln >> 4));
            uint32_t ahi[4], alo[4];
            ldsm4(ahi, ah_base + aoff);
            ldsm4(alo, al_base + aoff);
            #pragma unroll
            for (int nd2 = 0; nd2 < 4; nd2++) {
                int krow = kk * 16 + (ln & 7) + (ln & 8);
                int chnk = wh * 8 + nd2 * 2 + ((ln >> 4) & 1);
                uint32_t wf[4];
                ldsm4t(wf, sb + wboff + sw_off(krow, chnk));
                mma16816h(oacc[2 * nd2],     ahi, wf[0], wf[1]);
                mma16816h(oacc[2 * nd2 + 1], ahi, wf[2], wf[3]);
                mma16816h(oacc[2 * nd2],     alo, wf[0], wf[1]);
                mma16816h(oacc[2 * nd2 + 1], alo, wf[2], wf[3]);
            }
        }
        __syncthreads();    // all MMA reads of this W buffer done

        if (hh == 1) {
            // Epilogue for z: stage fp16-hi in the freed W buffer, 256 B rows.
            uint4* OH = (z == 0) ? g_Qhi : (z == 1) ? g_Khi : g_Vhi;
            const float scale = (z == 0) ? 0.0625f : 1.0f;
            const int r0 = wq * 16 + (ln >> 2);
            const int p0 = wh * 32 + (ln & 3);   // fp16x2 word index in row

            #pragma unroll
            for (int nt = 0; nt < 8; nt++) {
                int pi = p0 + nt * 4;
                *(uint32_t*)(smem + wboff + r0 * 256 + pi * 4) =
                    packh(oacc[nt][0] * scale, oacc[nt][1] * scale);
                *(uint32_t*)(smem + wboff + (r0 + 8) * 256 + pi * 4) =
                    packh(oacc[nt][2] * scale, oacc[nt][3] * scale);
            }
            __syncthreads();
            #pragma unroll
            for (int it = 0; it < 4; it++) {
                int idx = tid + it * 512;
                int r = idx >> 4, ch = idx & 15;
                uint4 v = *(uint4*)(smem + wboff + r * 256 + ch * 16);
                OH[(size_t)tile * 2048 + (sw_off(r, ch) >> 4)] = v;
            }
            __syncthreads();
        }

        // Prefetch chunk ci+2 into this (now fully free) buffer.
        if (ci + 2 < nc) {
            const uint4* src = g_Wh + (size_t)(ci + 2) * 2048;
            #pragma unroll
            for (int it = 0; it < 4; it++) {
                int c = tid + it * 512;
                CPA16(sb + wboff + c * 16, src + c);
            }
        }
        CPA_COMMIT();
    }
    CPA_WAIT(0);
}

// ---------------------------------------------------------------------------
// Kernel 2: mma.sync fp16 hi-only flash attention (QK and PV both 1-pass:
// 256 MMAs/warp/tile). LPT-ordered 1-D grid; boundary-only masking;
// pipelined K/V prefetch. 256 threads, 8 warps x 16 q-rows.
// ---------------------------------------------------------------------------
#define SMQH 0
#define SMKH 32768
#define SMVH 65536
#define ATTN_SMEM 98304

__global__ __launch_bounds__(256, 1) void attn_mma_kernel(
    const int* __restrict__ sen_len,
    float* __restrict__ out)
{
    extern __shared__ char smem[];
    const uint32_t sb = smem_u32(smem);

    const int tid = threadIdx.x;
    const int wid = tid >> 5;
    const int ln  = tid & 31;
    const int bid = blockIdx.x;
    const int b   = g_perm[bid >> 4];        // LPT: longest batches first
    const int qt  = bid & 15;
    const int q0  = qt * 128;
    const int L   = sen_len[b];
    const int ntiles = (L + 127) >> 7;
    const size_t tb0 = (size_t)(b * 16) * 2048;

    // ---- Prologue: group[Q+K0], group[V0] ----
    {
        const uint4* QH = g_Qhi + tb0 + (size_t)qt * 2048;
        #pragma unroll
        for (int it = 0; it < 8; it++) {
            int c = tid + it * 256;
            CPA16(sb + SMQH + c * 16, QH + c);
            CPA16(sb + SMKH + c * 16, g_Khi + tb0 + c);
        }
        CPA_COMMIT();
        #pragma unroll
        for (int it = 0; it < 8; it++) {
            int c = tid + it * 256;
            CPA16(sb + SMVH + c * 16, g_Vhi + tb0 + c);
        }
        CPA_COMMIT();
    }

    const int q0w = wid * 16;
    float oacc[16][4];
    #pragma unroll
    for (int nt = 0; nt < 16; nt++)
        #pragma unroll
        for (int j = 0; j < 4; j++) oacc[nt][j] = 0.0f;
    float lsum0 = 0.0f, lsum1 = 0.0f;

    for (int t = 0; t < ntiles; t++) {
        CPA_WAIT(1);        // Q+K(t) ready; V(t) may fly
        __syncthreads();

        // ---- S = Qhi Khi^T : 1-pass fp16, pair-interleaved ----
        float sacc[16][4];
        #pragma unroll
        for (int nt = 0; nt < 16; nt++)
            #pragma unroll
            for (int j = 0; j < 4; j++) sacc[nt][j] = 0.0f;

        const int keyb = (ln & 7) + ((ln & 16) >> 1);

        #pragma unroll
        for (int kk = 0; kk < 8; kk++) {
            const int chnk = kk * 2 + ((ln & 8) >> 3);
            uint32_t ahi[4];
            ldsm4(ahi, sb + SMQH + sw_off(q0w + (ln & 15), kk * 2 + (ln >> 4)));

            uint32_t bh[2][2][4];   // [buf][key-of-pair][frag]
            ldsm4(bh[0][0], sb + SMKH + sw_off(keyb,      chnk));
            ldsm4(bh[0][1], sb + SMKH + sw_off(keyb + 16, chnk));

            #pragma unroll
            for (int p = 0; p < 4; p++) {
                const int cur = p & 1, nxt = cur ^ 1;
                if (p < 3) {
                    int ky = keyb + (p + 1) * 32;
                    ldsm4(bh[nxt][0], sb + SMKH + sw_off(ky,      chnk));
                    ldsm4(bh[nxt][1], sb + SMKH + sw_off(ky + 16, chnk));
                }
                mma16816h(sacc[4 * p],     ahi, bh[cur][0][0], bh[cur][0][1]);
                mma16816h(sacc[4 * p + 1], ahi, bh[cur][0][2], bh[cur][0][3]);
                mma16816h(sacc[4 * p + 2], ahi, bh[cur][1][0], bh[cur][1][1]);
                mma16816h(sacc[4 * p + 3], ahi, bh[cur][1][2], bh[cur][1][3]);
            }
        }

        // ---- sK dead: prefetch K(t+1) (empty group on last tile) ----
        __syncthreads();
        if (t + 1 < ntiles) {
            const size_t tb = tb0 + (size_t)(t + 1) * 2048;
            #pragma unroll
            for (int it = 0; it < 8; it++) {
                int c = tid + it * 256;
                CPA16(sb + SMKH + c * 16, g_Khi + tb + c);
            }
        }
        CPA_COMMIT();

        // ---- Softmax (registers only; P fp16-hi). Boundary-only masking. ----
        uint32_t phi[8][4];
        const bool boundary = (t == ntiles - 1) && (L & 127);
        if (!boundary) {
            #pragma unroll
            for (int nt = 0; nt < 16; nt++) {
                float p0 = __expf(sacc[nt][0]);
                float p1 = __expf(sacc[nt][1]);
                float p2 = __expf(sacc[nt][2]);
                float p3 = __expf(sacc[nt][3]);
                lsum0 += p0 + p1;
                lsum1 += p2 + p3;
                phi[nt >> 1][(nt & 1) * 2]     = packh(p0, p1);
                phi[nt >> 1][(nt & 1) * 2 + 1] = packh(p2, p3);
            }
        } else {
            const int kb = t * 128 + 2 * (ln & 3);
            #pragma unroll
            for (int nt = 0; nt < 16; nt++) {
                int kcol = kb + nt * 8;
                float p0 = (kcol     < L) ? __expf(sacc[nt][0]) : 0.f;
                float p1 = (kcol + 1 < L) ? __expf(sacc[nt][1]) : 0.f;
                float p2 = (kcol     < L) ? __expf(sacc[nt][2]) : 0.f;
                float p3 = (kcol + 1 < L) ? __expf(sacc[nt][3]) : 0.f;
                lsum0 += p0 + p1;
                lsum1 += p2 + p3;
                phi[nt >> 1][(nt & 1) * 2]     = packh(p0, p1);
                phi[nt >> 1][(nt & 1) * 2 + 1] = packh(p2, p3);
            }
        }

        CPA_WAIT(1);        // V(t) ready (K(t+1) in flight)
        __syncthreads();

        // ---- O += Phi Vhi : 1-pass fp16, pair-interleaved ----
        const int keyr0 = (ln & 7) + (ln & 8);
        #pragma unroll
        for (int kk = 0; kk < 8; kk++) {
            const int keyr = kk * 16 + keyr0;
            const int ch0  = (ln >> 4) & 1;

            uint32_t vh[2][2][4];   // [buf][d-of-pair][frag]
            ldsm4t(vh[0][0], sb + SMVH + sw_off(keyr, ch0));
            ldsm4t(vh[0][1], sb + SMVH + sw_off(keyr, ch0 + 2));

            #pragma unroll
            for (int p = 0; p < 4; p++) {
                const int cur = p & 1, nxt = cur ^ 1;
                if (p < 3) {
                    int ch = ch0 + (p + 1) * 4;
                    ldsm4t(vh[nxt][0], sb + SMVH + sw_off(keyr, ch));
                    ldsm4t(vh[nxt][1], sb + SMVH + sw_off(keyr, ch + 2));
                }
                mma16816h(oacc[4 * p],     phi[kk], vh[cur][0][0], vh[cur][0][1]);
                mma16816h(oacc[4 * p + 1], phi[kk], vh[cur][0][2], vh[cur][0][3]);
                mma16816h(oacc[4 * p + 2], phi[kk], vh[cur][1][0], vh[cur][1][1]);
                mma16816h(oacc[4 * p + 3], phi[kk], vh[cur][1][2], vh[cur][1][3]);
            }
        }

        // ---- sV dead: prefetch V(t+1) (empty group on last tile) ----
        __syncthreads();
        if (t + 1 < ntiles) {
            const size_t tb = tb0 + (size_t)(t + 1) * 2048;
            #pragma unroll
            for (int it = 0; it < 8; it++) {
                int c = tid + it * 256;
                CPA16(sb + SMVH + c * 16, g_Vhi + tb + c);
            }
        }
        CPA_COMMIT();
    }
    CPA_WAIT(0);   // drain trailing empty groups

    // ---- Epilogue ----
    #pragma unroll
    for (int off = 1; off < 4; off <<= 1) {
        lsum0 += __shfl_xor_sync(0xffffffffu, lsum0, off);
        lsum1 += __shfl_xor_sync(0xffffffffu, lsum1, off);
    }
    const float inv0 = 1.0f / lsum0;
    const float inv1 = 1.0f / lsum1;

    const int g    = ln >> 2;
    const int tid4 = ln & 3;
    const int row  = q0 + q0w + g;
    float* o0 = &out[((size_t)b * S_ + row) * DATT_];
    float* o1 = &out[((size_t)b * S_ + row + 8) * DATT_];
    #pragma unroll
    for (int nt = 0; nt < 16; nt++) {
        int c = nt * 8 + 2 * tid4;
        *(float2*)(o0 + c) = make_float2(oacc[nt][0] * inv0, oacc[nt][1] * inv0);
        *(float2*)(o1 + c) = make_float2(oacc[nt][2] * inv1, oacc[nt][3] * inv1);
    }
}

// ---------------------------------------------------------------------------
extern "C" void kernel_launch(void* const* d_in, const int* in_sizes, int n_in,
                              void* d_out, int out_size)
{
    (void)in_sizes; (void)n_in; (void)out_size;
    const float* inputs  = (const float*)d_in[0];
    const int*   sen_len = (const int*)  d_in[1];
    const float* Wq      = (const float*)d_in[2];
    const float* Wk      = (const float*)d_in[3];
    const float* Wv      = (const float*)d_in[4];
    float* out = (float*)d_out;

    setup_kernel<<<12, 256>>>(Wq, Wk, Wv, sen_len);

    cudaFuncSetAttribute(qkv_fused_kernel,
                         cudaFuncAttributeMaxDynamicSharedMemorySize, QKV_SMEM);
    qkv_fused_kernel<<<NTILE, 512, QKV_SMEM>>>(inputs, sen_len);

    cudaFuncSetAttribute(attn_mma_kernel,
                         cudaFuncAttributeMaxDynamicSharedMemorySize, ATTN_SMEM);
    attn_mma_kernel<<<NTILE, 256, ATTN_SMEM>>>(sen_len, out);
}